// round 12
// baseline (speedup 1.0000x reference)
#include <cuda_runtime.h>
#include <cuda_fp16.h>
#include <cstdint>

#define BB 512
#define SS 200
#define DD 512
#define HH 8
#define DHH 64
#define MM (BB*SS)          // 102400 rows

// ---------------------------------------------------------------------------
// Scratch (device globals; no allocations anywhere)
// ---------------------------------------------------------------------------
__device__ __half g_hh  [(size_t)MM * DD];        // fp16 LN(x): GEMM A + residual
__device__ __half g_qkv [(size_t)MM * 3 * DD];    // fp16 [M,1536] q|k|v (featmap fused)
__device__ __half g_ctxh[(size_t)MM * DD];        // fp16 ctx for GEMM2 A
__device__ __half g_oh  [(size_t)MM * DD];        // fp16 out-proj result
__device__ __half g_WtQKV[(size_t)3 * DD * DD];   // [1536][512] = W^T fp16
__device__ __half g_WtD  [(size_t)DD * DD];       // [512][512]  = Wd^T fp16
__device__ float  g_bqkv [3 * DD];

// ---------------------------------------------------------------------------
// Helpers
// ---------------------------------------------------------------------------
__device__ __forceinline__ uint32_t smem_u32(const void* p) {
    uint32_t a;
    asm("{ .reg .u64 t; cvta.to.shared.u64 t, %1; cvt.u32.u64 %0, t; }"
        : "=r"(a) : "l"(p));
    return a;
}
#define CPASYNC16(dst, src) \
    asm volatile("cp.async.cg.shared.global [%0], [%1], 16;" :: "r"(dst), "l"(src) : "memory")
#define CP_COMMIT() asm volatile("cp.async.commit_group;" ::: "memory")
#define CP_WAIT0()  asm volatile("cp.async.wait_group 0;" ::: "memory")
#define CP_WAIT1()  asm volatile("cp.async.wait_group 1;" ::: "memory")
#define SWZ(o) ((o) ^ (((o) >> 3) & 0x70))
#define LDSM4(r0, r1, r2, r3, a) \
    asm volatile("ldmatrix.sync.aligned.m8n8.x4.shared.b16 {%0,%1,%2,%3}, [%4];" \
                 : "=r"(r0), "=r"(r1), "=r"(r2), "=r"(r3) : "r"(a))
#define LDSM4T(r0, r1, r2, r3, a) \
    asm volatile("ldmatrix.sync.aligned.m8n8.x4.trans.shared.b16 {%0,%1,%2,%3}, [%4];" \
                 : "=r"(r0), "=r"(r1), "=r"(r2), "=r"(r3) : "r"(a))
#define MMA16816(c0,c1,c2,c3,a0,a1,a2,a3,b0,b1) \
    asm volatile("mma.sync.aligned.m16n8k16.row.col.f32.f16.f16.f32 " \
                 "{%0,%1,%2,%3},{%4,%5,%6,%7},{%8,%9},{%0,%1,%2,%3};" \
                 : "+f"(c0), "+f"(c1), "+f"(c2), "+f"(c3) \
                 : "r"(a0), "r"(a1), "r"(a2), "r"(a3), "r"(b0), "r"(b1))

// ---------------------------------------------------------------------------
// Weight transpose + fp16: Wt[n][k] = fp16(W[k][n]). grid (16,16,4), block (32,8)
// ---------------------------------------------------------------------------
__global__ void pack_wt(const float* __restrict__ Wq, const float* __restrict__ Wk,
                        const float* __restrict__ Wv, const float* __restrict__ Wd) {
    __shared__ float t[32][33];
    int z = blockIdx.z;
    const float* W = z == 0 ? Wq : z == 1 ? Wk : z == 2 ? Wv : Wd;
    int x0 = blockIdx.x * 32, y0 = blockIdx.y * 32;
    int tx = threadIdx.x, ty = threadIdx.y;
#pragma unroll
    for (int i = 0; i < 32; i += 8)
        t[ty + i][tx] = W[(size_t)(y0 + ty + i) * 512 + x0 + tx];
    __syncthreads();
    __half* dst = (z < 3) ? (g_WtQKV + (size_t)z * 512 * 512) : g_WtD;
#pragma unroll
    for (int i = 0; i < 32; i += 8)
        dst[(size_t)(x0 + ty + i) * 512 + y0 + tx] = __float2half_rn(t[tx][ty + i]);
}

__global__ void pack_bias(const float* __restrict__ bq, const float* __restrict__ bk,
                          const float* __restrict__ bv) {
    int i = blockIdx.x * 256 + threadIdx.x;
    if (i < 512) { g_bqkv[i] = bq[i]; g_bqkv[512 + i] = bk[i]; g_bqkv[1024 + i] = bv[i]; }
}

// ---------------------------------------------------------------------------
// Block reduce (128 threads, 2 values)
// ---------------------------------------------------------------------------
__device__ __forceinline__ void block_reduce2_128(float& a, float& b) {
#pragma unroll
    for (int o = 16; o > 0; o >>= 1) {
        a += __shfl_xor_sync(0xffffffffu, a, o);
        b += __shfl_xor_sync(0xffffffffu, b, o);
    }
    __shared__ float sa[4], sb[4];
    int w = threadIdx.x >> 5, l = threadIdx.x & 31;
    if (l == 0) { sa[w] = a; sb[w] = b; }
    __syncthreads();
    a = sa[0] + sa[1] + sa[2] + sa[3];
    b = sb[0] + sb[1] + sb[2] + sb[3];
}

// ---------------------------------------------------------------------------
// h = LayerNorm(input + pos); write fp16 only (GEMM A + residual)
// ---------------------------------------------------------------------------
__global__ void add_ln(const float* __restrict__ x, const float* __restrict__ p,
                       const float* __restrict__ g, const float* __restrict__ b) {
    size_t row = blockIdx.x;
    int t = threadIdx.x;
    float4 xv = ((const float4*)x)[row * 128 + t];
    float4 pv = ((const float4*)p)[row * 128 + t];
    xv.x += pv.x; xv.y += pv.y; xv.z += pv.z; xv.w += pv.w;
    float s  = xv.x + xv.y + xv.z + xv.w;
    float ss = xv.x*xv.x + xv.y*xv.y + xv.z*xv.z + xv.w*xv.w;
    block_reduce2_128(s, ss);
    float mu  = s * (1.0f / 512.0f);
    float var = ss * (1.0f / 512.0f) - mu * mu;
    float rstd = rsqrtf(var + 1e-12f);
    float4 gv = ((const float4*)g)[t];
    float4 bv = ((const float4*)b)[t];
    float4 o;
    o.x = (xv.x - mu) * rstd * gv.x + bv.x;
    o.y = (xv.y - mu) * rstd * gv.y + bv.y;
    o.z = (xv.z - mu) * rstd * gv.z + bv.z;
    o.w = (xv.w - mu) * rstd * gv.w + bv.w;
    __half2 h01 = __floats2half2_rn(o.x, o.y);
    __half2 h23 = __floats2half2_rn(o.z, o.w);
    uint2 u; u.x = *(uint32_t*)&h01; u.y = *(uint32_t*)&h23;
    ((uint2*)g_hh)[row * 128 + t] = u;
}

// ---------------------------------------------------------------------------
// fp16 GEMM (mma.sync + ldmatrix, 3-stage cp.async, unrolled kt):
//   C = A[M,512]*Bt^T + bias. Block tile 128(M) x 128(N), 4 warps, warp 64x64.
//   mode 0: QKV + featmap -> g_qkv fp16. mode 1: -> g_oh fp16
// ---------------------------------------------------------------------------
#define STAGE_BYTES 32768            // A 16KB + B 16KB
#define GEMM_SMEM   (3 * STAGE_BYTES)

__global__ void __launch_bounds__(128, 2) gemm_f16(int mode, const float* __restrict__ extB) {
    const __half* A; const __half* Bt; const float* bias; int N, fuse;
    if (mode == 0) { A = g_hh;   Bt = g_WtQKV; bias = g_bqkv; N = 1536; fuse = 1; }
    else           { A = g_ctxh; Bt = g_WtD;   bias = extB;   N = 512;  fuse = 0; }

    extern __shared__ char sm[];
    int tid = threadIdx.x, warp = tid >> 5, lane = tid & 31;
    int wm = warp >> 1, wn = warp & 1;           // 2 x 2 warp grid, warp tile 64x64
    int gid = lane >> 2, tig = lane & 3;
    int m0 = blockIdx.y * 128, n0 = blockIdx.x * 128;
    uint32_t sb = smem_u32(sm);

    uint32_t aOff[4], aXr[4];
    uint32_t aKb = (lane >> 4) * 16;
    {
        int jlo = (lane >> 3) & 1, i = lane & 7;
#pragma unroll
        for (int ii = 0; ii < 4; ii++) {
            int m = 64 * wm + 16 * ii + jlo * 8 + i;
            aOff[ii] = m * 128;
            aXr[ii]  = (m & 7) * 16;
        }
    }
    uint32_t bOff[4], bXr[4];
    uint32_t bKb = ((lane >> 3) & 1) * 16;
    {
        int i = lane & 7;
#pragma unroll
        for (int g = 0; g < 4; g++) {
            int n = 64 * wn + 8 * (2 * g + (lane >> 4)) + i;
            bOff[g] = 16384 + n * 128;
            bXr[g]  = (n & 7) * 16;
        }
    }

    float acc[4][8][4];
#pragma unroll
    for (int i = 0; i < 4; i++)
#pragma unroll
        for (int j = 0; j < 8; j++)
#pragma unroll
            for (int k = 0; k < 4; k++) acc[i][j][k] = 0.0f;

    auto load_stage = [&](int s, int kt) {
        uint32_t ad = sb + s * STAGE_BYTES;
        const __half* Ag = A + (size_t)m0 * 512 + kt * 64;
#pragma unroll
        for (int i = 0; i < 8; i++) {
            int idx = i * 128 + tid;
            int r = idx >> 3, c = idx & 7;
            CPASYNC16(ad + SWZ(r * 128 + c * 16), Ag + (size_t)r * 512 + c * 8);
        }
        uint32_t bd = ad + 16384;
        const __half* Bg = Bt + (size_t)n0 * 512 + kt * 64;
#pragma unroll
        for (int i = 0; i < 8; i++) {
            int idx = i * 128 + tid;
            int r = idx >> 3, c = idx & 7;
            CPASYNC16(bd + SWZ(r * 128 + c * 16), Bg + (size_t)r * 512 + c * 8);
        }
        CP_COMMIT();
    };

    load_stage(0, 0);
    load_stage(1, 1);
#pragma unroll
    for (int kt = 0; kt < 8; ++kt) {
        if (kt < 7) CP_WAIT1(); else CP_WAIT0();
        __syncthreads();
        if (kt + 2 < 8) load_stage((kt + 2) % 3, kt + 2);

        uint32_t stg = sb + (kt % 3) * STAGE_BYTES;
#pragma unroll
        for (int ks = 0; ks < 4; ks++) {
            uint32_t kbyte = ks * 32;
            uint32_t bfr[8][2];
#pragma unroll
            for (int g = 0; g < 4; g++) {
                uint32_t addr = stg + bOff[g] + ((kbyte + bKb) ^ bXr[g]);
                LDSM4(bfr[2*g][0], bfr[2*g][1], bfr[2*g+1][0], bfr[2*g+1][1], addr);
            }
#pragma unroll
            for (int i = 0; i < 4; i++) {
                uint32_t a0, a1, a2, a3;
                uint32_t addr = stg + aOff[i] + ((kbyte + aKb) ^ aXr[i]);
                LDSM4(a0, a1, a2, a3, addr);
#pragma unroll
                for (int j = 0; j < 8; j++)
                    MMA16816(acc[i][j][0], acc[i][j][1], acc[i][j][2], acc[i][j][3],
                             a0, a1, a2, a3, bfr[j][0], bfr[j][1]);
            }
        }
    }

    // Epilogue: bias (+ fused ELU + per-head L2 norm for q,k), store fp16
    float bv[16];
#pragma unroll
    for (int j = 0; j < 8; j++) {
        int col = n0 + 64 * wn + 8 * j + 2 * tig;
        bv[2*j]   = __ldg(bias + col);
        bv[2*j+1] = __ldg(bias + col + 1);
    }
    bool dof = fuse && (n0 + 64 * wn) < 1024;
#pragma unroll
    for (int i = 0; i < 4; i++) {
#pragma unroll
        for (int hr = 0; hr < 2; hr++) {
            float v[16];
#pragma unroll
            for (int j = 0; j < 8; j++) {
                v[2*j]   = acc[i][j][2*hr]     + bv[2*j];
                v[2*j+1] = acc[i][j][2*hr + 1] + bv[2*j+1];
            }
            if (dof) {
                float ss = 0.0f;
#pragma unroll
                for (int t = 0; t < 16; t++) {
                    v[t] = v[t] > 0.0f ? v[t] : expm1f(v[t]);
                    ss += v[t] * v[t];
                }
                ss += __shfl_xor_sync(0xffffffffu, ss, 1);
                ss += __shfl_xor_sync(0xffffffffu, ss, 2);
                float rn = rsqrtf(ss);
#pragma unroll
                for (int t = 0; t < 16; t++) v[t] *= rn;
            }
            int row = m0 + 64 * wm + 16 * i + 8 * hr + gid;
            __half* cp = (mode == 0)
                ? g_qkv + (size_t)row * 1536 + n0 + 64 * wn + 2 * tig
                : g_oh  + (size_t)row * 512  + n0 + 64 * wn + 2 * tig;
#pragma unroll
            for (int j = 0; j < 8; j++) {
                __half2 hv = __floats2half2_rn(v[2*j], v[2*j+1]);
                *(uint32_t*)(cp + 8 * j) = *(uint32_t*)&hv;
            }
        }
    }
}

// ---------------------------------------------------------------------------
// Fused linear attention per (b,h): KV = kn^T v ; ctx = qn KV / 8  (all HMMA)
//   smem: qn/kn/v [208 x 64] fp16 swizzled (rows 200..207 zero) + KV [64x64] fp16
// ---------------------------------------------------------------------------
#define SP 208
#define T_Q 0
#define T_K (SP * 128)
#define T_V (2 * SP * 128)
#define T_KV (3 * SP * 128)
#define ATTN_SMEM (3 * SP * 128 + 64 * 128)

__global__ void __launch_bounds__(256, 2) fused_attn() {
    extern __shared__ char sm[];
    uint32_t sb = smem_u32(sm);
    int tid = threadIdx.x, warp = tid >> 5, lane = tid & 31;
    int gid = lane >> 2, tig = lane & 3;
    int bh = blockIdx.x;
    int b = bh >> 3, h = bh & 7;

    // ---- load qn, kn, v tiles (200 rows x 64 halves each) ----
    const __half* base = g_qkv + (size_t)b * 200 * 1536 + h * 64;
    for (int i = tid; i < 1600; i += 256) {
        int r = i >> 3, c = i & 7;
        size_t off = (size_t)r * 1536 + c * 8;
        uint32_t sw = SWZ(r * 128 + c * 16);
        CPASYNC16(sb + T_Q + sw, base + off);
        CPASYNC16(sb + T_K + sw, base + 512 + off);
        CPASYNC16(sb + T_V + sw, base + 1024 + off);
    }
    CP_COMMIT();
    // zero pad rows 200..207
    if (tid < 192) {
        int t = tid >> 6, rem = tid & 63;
        int r = 200 + (rem >> 3), c = rem & 7;
        uint32_t sw = SWZ(r * 128 + c * 16);
        uint32_t tb = (t == 0) ? T_Q : (t == 1) ? T_K : T_V;
        *(uint4*)(sm + tb + sw) = make_uint4(0, 0, 0, 0);
    }
    CP_WAIT0();
    __syncthreads();

    // ---- phase 1: KV[d,e] = sum_s kn[s,d] * v[s,e]  (warp grid 4x2, tile 16x32)
    int wm = warp >> 1, wn = warp & 1;
    int d0 = 16 * wm, e0 = 32 * wn;
    float acc1[4][4];
#pragma unroll
    for (int j = 0; j < 4; j++)
#pragma unroll
        for (int k = 0; k < 4; k++) acc1[j][k] = 0.0f;

    int sA_l = (lane & 7) + 8 * (lane >> 4);
    int dA = d0 + 8 * ((lane >> 3) & 1);
    int sB_l = (lane & 7) + 8 * ((lane >> 3) & 1);
    int eB_l = 8 * (lane >> 4);

#pragma unroll
    for (int ks = 0; ks < 13; ks++) {
        int s0 = ks * 16;
        uint32_t a0, a1, a2, a3;
        {
            int sA = s0 + sA_l;
            uint32_t addr = sb + T_K + sA * 128 + ((dA * 2) ^ ((sA & 7) * 16));
            LDSM4T(a0, a1, a2, a3, addr);
        }
        uint32_t bfr[4][2];
#pragma unroll
        for (int g = 0; g < 2; g++) {
            int sB = s0 + sB_l;
            int eB = e0 + 16 * g + eB_l;
            uint32_t addr = sb + T_V + sB * 128 + ((eB * 2) ^ ((sB & 7) * 16));
            LDSM4T(bfr[2*g][0], bfr[2*g][1], bfr[2*g+1][0], bfr[2*g+1][1], addr);
        }
#pragma unroll
        for (int j = 0; j < 4; j++)
            MMA16816(acc1[j][0], acc1[j][1], acc1[j][2], acc1[j][3],
                     a0, a1, a2, a3, bfr[j][0], bfr[j][1]);
    }
    // store KV (fp16, swizzled) to smem
#pragma unroll
    for (int j = 0; j < 4; j++) {
#pragma unroll
        for (int hr = 0; hr < 2; hr++) {
            int row = d0 + 8 * hr + gid;
            int colb = (32 * wn + 8 * j + 2 * tig) * 2;
            __half2 hv = __floats2half2_rn(acc1[j][2*hr], acc1[j][2*hr+1]);
            *(uint32_t*)(sm + T_KV + row * 128 + (colb ^ ((row & 7) * 16))) = *(uint32_t*)&hv;
        }
    }
    __syncthreads();

    // ---- phase 2: ctx[s,e] = (1/8) sum_d qn[s,d] * KV[d,e] ----
    int rA_l = (lane & 7) + 8 * ((lane >> 3) & 1);
    int cA_l = 8 * (lane >> 4);
    int dB_l = (lane & 7) + 8 * ((lane >> 3) & 1);
    int eB2_l = 8 * (lane >> 4);

#pragma unroll
    for (int rep = 0; rep < 2; rep++) {
        int mt = warp + 8 * rep;
        if (mt > 12) break;
        int s0 = mt * 16;
        float acc2[8][4];
#pragma unroll
        for (int j = 0; j < 8; j++)
#pragma unroll
            for (int k = 0; k < 4; k++) acc2[j][k] = 0.0f;

#pragma unroll
        for (int kk = 0; kk < 4; kk++) {
            int kd0 = kk * 16;
            uint32_t a0, a1, a2, a3;
            {
                int r = s0 + rA_l;
                int dc = kd0 + cA_l;
                uint32_t addr = sb + T_Q + r * 128 + ((dc * 2) ^ ((r & 7) * 16));
                LDSM4(a0, a1, a2, a3, addr);
            }
            uint32_t bfr[8][2];
#pragma unroll
            for (int g = 0; g < 4; g++) {
                int dB = kd0 + dB_l;
                int eB = 16 * g + eB2_l;
                uint32_t addr = sb + T_KV + dB * 128 + ((eB * 2) ^ ((dB & 7) * 16));
                LDSM4T(bfr[2*g][0], bfr[2*g][1], bfr[2*g+1][0], bfr[2*g+1][1], addr);
            }
#pragma unroll
            for (int j = 0; j < 8; j++)
                MMA16816(acc2[j][0], acc2[j][1], acc2[j][2], acc2[j][3],
                         a0, a1, a2, a3, bfr[j][0], bfr[j][1]);
        }
        // store ctx rows (guard s < 200)
#pragma unroll
        for (int hr = 0; hr < 2; hr++) {
            int s = s0 + 8 * hr + gid;
            if (s < 200) {
                __half* cp = g_ctxh + ((size_t)b * 200 + s) * 512 + h * 64 + 2 * tig;
#pragma unroll
                for (int j = 0; j < 8; j++) {
                    __half2 hv = __floats2half2_rn(acc2[j][2*hr] * 0.125f,
                                                   acc2[j][2*hr+1] * 0.125f);
                    *(uint32_t*)(cp + 8 * j) = *(uint32_t*)&hv;
                }
            }
        }
    }
}

// ---------------------------------------------------------------------------
// out = LayerNorm(g_oh + g_hh)   (both residual inputs fp16)
// ---------------------------------------------------------------------------
__global__ void final_ln(const float* __restrict__ g, const float* __restrict__ bv_,
                         float* __restrict__ out) {
    size_t row = blockIdx.x;
    int t = threadIdx.x;
    uint2 ou = ((const uint2*)g_oh)[row * 128 + t];
    uint2 hu = ((const uint2*)g_hh)[row * 128 + t];
    float2 o01 = __half22float2(*(__half2*)&ou.x);
    float2 o23 = __half22float2(*(__half2*)&ou.y);
    float2 h01 = __half22float2(*(__half2*)&hu.x);
    float2 h23 = __half22float2(*(__half2*)&hu.y);
    float4 ov;
    ov.x = o01.x + h01.x; ov.y = o01.y + h01.y;
    ov.z = o23.x + h23.x; ov.w = o23.y + h23.y;
    float s  = ov.x + ov.y + ov.z + ov.w;
    float ss = ov.x*ov.x + ov.y*ov.y + ov.z*ov.z + ov.w*ov.w;
    block_reduce2_128(s, ss);
    float mu  = s * (1.0f / 512.0f);
    float var = ss * (1.0f / 512.0f) - mu * mu;
    float rstd = rsqrtf(var + 1e-12f);
    float4 gv = ((const float4*)g)[t];
    float4 bb = ((const float4*)bv_)[t];
    float4 o;
    o.x = (ov.x - mu) * rstd * gv.x + bb.x;
    o.y = (ov.y - mu) * rstd * gv.y + bb.y;
    o.z = (ov.z - mu) * rstd * gv.z + bb.z;
    o.w = (ov.w - mu) * rstd * gv.w + bb.w;
    ((float4*)out)[row * 128 + t] = o;
}

// ---------------------------------------------------------------------------
// Launch
// ---------------------------------------------------------------------------
extern "C" void kernel_launch(void* const* d_in, const int* in_sizes, int n_in,
                              void* d_out, int out_size) {
    const float* input = (const float*)d_in[0];
    const float* pos   = (const float*)d_in[1];
    // d_in[2] = attention_mask (unused by LinMHA)
    const float* Wq = (const float*)d_in[3];
    const float* bq = (const float*)d_in[4];
    const float* Wk = (const float*)d_in[5];
    const float* bk = (const float*)d_in[6];
    const float* Wv = (const float*)d_in[7];
    const float* bv = (const float*)d_in[8];
    const float* Wd = (const float*)d_in[9];
    const float* bd = (const float*)d_in[10];
    const float* lng = (const float*)d_in[11];
    const float* lnb = (const float*)d_in[12];
    float* out = (float*)d_out;

    static bool attr_set = false;
    if (!attr_set) {
        cudaFuncSetAttribute(gemm_f16, cudaFuncAttributeMaxDynamicSharedMemorySize, GEMM_SMEM);
        cudaFuncSetAttribute(fused_attn, cudaFuncAttributeMaxDynamicSharedMemorySize, ATTN_SMEM);
        attr_set = true;
    }

    pack_wt<<<dim3(16, 16, 4), dim3(32, 8)>>>(Wq, Wk, Wv, Wd);
    pack_bias<<<2, 256>>>(bq, bk, bv);
    add_ln<<<MM, 128>>>(input, pos, lng, lnb);
    gemm_f16<<<dim3(12, 800), 128, GEMM_SMEM>>>(0, nullptr);   // QKV + featmap
    fused_attn<<<4096, 256, ATTN_SMEM>>>();                    // kv + ctx
    gemm_f16<<<dim3(4, 800), 128, GEMM_SMEM>>>(1, bd);         // output proj
    final_ln<<<MM, 128>>>(lng, lnb, out);
}

// round 13
// speedup vs baseline: 1.0964x; 1.0964x over previous
#include <cuda_runtime.h>
#include <cuda_fp16.h>
#include <cstdint>

#define BB 512
#define SS 200
#define DD 512
#define HH 8
#define DHH 64
#define MM (BB*SS)          // 102400 rows

// ---------------------------------------------------------------------------
// Scratch (device globals; no allocations anywhere)
// ---------------------------------------------------------------------------
__device__ __half g_hh  [(size_t)MM * DD];        // fp16 LN(x): GEMM A + residual
__device__ __half g_qkv [(size_t)MM * 3 * DD];    // fp16 [M,1536] q|k|v (featmap fused)
__device__ __half g_ctxh[(size_t)MM * DD];        // fp16 ctx for GEMM2 A
__device__ __half g_oh  [(size_t)MM * DD];        // fp16 out-proj result
__device__ __half g_WtQKV[(size_t)3 * DD * DD];   // [1536][512] = W^T fp16
__device__ __half g_WtD  [(size_t)DD * DD];       // [512][512]  = Wd^T fp16
__device__ float  g_bqkv [3 * DD];

// ---------------------------------------------------------------------------
// Helpers
// ---------------------------------------------------------------------------
__device__ __forceinline__ uint32_t smem_u32(const void* p) {
    uint32_t a;
    asm("{ .reg .u64 t; cvta.to.shared.u64 t, %1; cvt.u32.u64 %0, t; }"
        : "=r"(a) : "l"(p));
    return a;
}
#define CPASYNC16(dst, src) \
    asm volatile("cp.async.cg.shared.global [%0], [%1], 16;" :: "r"(dst), "l"(src) : "memory")
#define CP_COMMIT() asm volatile("cp.async.commit_group;" ::: "memory")
#define CP_WAIT0()  asm volatile("cp.async.wait_group 0;" ::: "memory")
#define CP_WAIT1()  asm volatile("cp.async.wait_group 1;" ::: "memory")
#define SWZ(o) ((o) ^ (((o) >> 3) & 0x70))
#define LDSM4(r0, r1, r2, r3, a) \
    asm volatile("ldmatrix.sync.aligned.m8n8.x4.shared.b16 {%0,%1,%2,%3}, [%4];" \
                 : "=r"(r0), "=r"(r1), "=r"(r2), "=r"(r3) : "r"(a))
#define LDSM4T(r0, r1, r2, r3, a) \
    asm volatile("ldmatrix.sync.aligned.m8n8.x4.trans.shared.b16 {%0,%1,%2,%3}, [%4];" \
                 : "=r"(r0), "=r"(r1), "=r"(r2), "=r"(r3) : "r"(a))
#define MMA16816(c0,c1,c2,c3,a0,a1,a2,a3,b0,b1) \
    asm volatile("mma.sync.aligned.m16n8k16.row.col.f32.f16.f16.f32 " \
                 "{%0,%1,%2,%3},{%4,%5,%6,%7},{%8,%9},{%0,%1,%2,%3};" \
                 : "+f"(c0), "+f"(c1), "+f"(c2), "+f"(c3) \
                 : "r"(a0), "r"(a1), "r"(a2), "r"(a3), "r"(b0), "r"(b1))

// ---------------------------------------------------------------------------
// Weight transpose + fp16: Wt[n][k] = fp16(W[k][n]). grid (16,16,4), block (32,8)
// ---------------------------------------------------------------------------
__global__ void pack_wt(const float* __restrict__ Wq, const float* __restrict__ Wk,
                        const float* __restrict__ Wv, const float* __restrict__ Wd) {
    __shared__ float t[32][33];
    int z = blockIdx.z;
    const float* W = z == 0 ? Wq : z == 1 ? Wk : z == 2 ? Wv : Wd;
    int x0 = blockIdx.x * 32, y0 = blockIdx.y * 32;
    int tx = threadIdx.x, ty = threadIdx.y;
#pragma unroll
    for (int i = 0; i < 32; i += 8)
        t[ty + i][tx] = W[(size_t)(y0 + ty + i) * 512 + x0 + tx];
    __syncthreads();
    __half* dst = (z < 3) ? (g_WtQKV + (size_t)z * 512 * 512) : g_WtD;
#pragma unroll
    for (int i = 0; i < 32; i += 8)
        dst[(size_t)(x0 + ty + i) * 512 + y0 + tx] = __float2half_rn(t[tx][ty + i]);
}

__global__ void pack_bias(const float* __restrict__ bq, const float* __restrict__ bk,
                          const float* __restrict__ bv) {
    int i = blockIdx.x * 256 + threadIdx.x;
    if (i < 512) { g_bqkv[i] = bq[i]; g_bqkv[512 + i] = bk[i]; g_bqkv[1024 + i] = bv[i]; }
}

// ---------------------------------------------------------------------------
// Block reduce (128 threads, 2 values)
// ---------------------------------------------------------------------------
__device__ __forceinline__ void block_reduce2_128(float& a, float& b) {
#pragma unroll
    for (int o = 16; o > 0; o >>= 1) {
        a += __shfl_xor_sync(0xffffffffu, a, o);
        b += __shfl_xor_sync(0xffffffffu, b, o);
    }
    __shared__ float sa[4], sb[4];
    int w = threadIdx.x >> 5, l = threadIdx.x & 31;
    if (l == 0) { sa[w] = a; sb[w] = b; }
    __syncthreads();
    a = sa[0] + sa[1] + sa[2] + sa[3];
    b = sb[0] + sb[1] + sb[2] + sb[3];
}

// ---------------------------------------------------------------------------
// h = LayerNorm(input + pos); write fp16 only (GEMM A + residual)
// ---------------------------------------------------------------------------
__global__ void add_ln(const float* __restrict__ x, const float* __restrict__ p,
                       const float* __restrict__ g, const float* __restrict__ b) {
    size_t row = blockIdx.x;
    int t = threadIdx.x;
    float4 xv = ((const float4*)x)[row * 128 + t];
    float4 pv = ((const float4*)p)[row * 128 + t];
    xv.x += pv.x; xv.y += pv.y; xv.z += pv.z; xv.w += pv.w;
    float s  = xv.x + xv.y + xv.z + xv.w;
    float ss = xv.x*xv.x + xv.y*xv.y + xv.z*xv.z + xv.w*xv.w;
    block_reduce2_128(s, ss);
    float mu  = s * (1.0f / 512.0f);
    float var = ss * (1.0f / 512.0f) - mu * mu;
    float rstd = rsqrtf(var + 1e-12f);
    float4 gv = ((const float4*)g)[t];
    float4 bv = ((const float4*)b)[t];
    float4 o;
    o.x = (xv.x - mu) * rstd * gv.x + bv.x;
    o.y = (xv.y - mu) * rstd * gv.y + bv.y;
    o.z = (xv.z - mu) * rstd * gv.z + bv.z;
    o.w = (xv.w - mu) * rstd * gv.w + bv.w;
    __half2 h01 = __floats2half2_rn(o.x, o.y);
    __half2 h23 = __floats2half2_rn(o.z, o.w);
    uint2 u; u.x = *(uint32_t*)&h01; u.y = *(uint32_t*)&h23;
    ((uint2*)g_hh)[row * 128 + t] = u;
}

// ---------------------------------------------------------------------------
// fp16 GEMM (mma.sync + ldmatrix, 3-stage cp.async, unrolled kt):
//   C = A[M,512]*Bt^T + bias. Block tile 256(M) x 128(N), 16 warps,
//   warp tile 32x64 (proven 128-reg config). B stage serves 2x the M-rows.
//   mode 0: QKV + featmap -> g_qkv fp16. mode 1: -> g_oh fp16
// ---------------------------------------------------------------------------
#define A_BYTES     32768            // 256 rows x 64 k x 2B
#define B_BYTES     16384            // 128 cols x 64 k x 2B
#define STAGE_BYTES (A_BYTES + B_BYTES)
#define GEMM_SMEM   (3 * STAGE_BYTES)   // 144KB -> 1 CTA/SM, 16 warps

__global__ void __launch_bounds__(512, 1) gemm_f16(int mode, const float* __restrict__ extB) {
    const __half* A; const __half* Bt; const float* bias; int N, fuse;
    if (mode == 0) { A = g_hh;   Bt = g_WtQKV; bias = g_bqkv; N = 1536; fuse = 1; }
    else           { A = g_ctxh; Bt = g_WtD;   bias = extB;   N = 512;  fuse = 0; }

    extern __shared__ char sm[];
    int tid = threadIdx.x, warp = tid >> 5, lane = tid & 31;
    int wm = warp >> 1, wn = warp & 1;           // 8 x 2 warp grid, warp tile 32x64
    int gid = lane >> 2, tig = lane & 3;
    int m0 = blockIdx.y * 256, n0 = blockIdx.x * 128;
    uint32_t sb = smem_u32(sm);

    uint32_t aOff[2], aXr[2];
    uint32_t aKb = (lane >> 4) * 16;
    {
        int jlo = (lane >> 3) & 1, i = lane & 7;
#pragma unroll
        for (int ii = 0; ii < 2; ii++) {
            int m = 32 * wm + 16 * ii + jlo * 8 + i;
            aOff[ii] = m * 128;
            aXr[ii]  = (m & 7) * 16;
        }
    }
    uint32_t bOff[4], bXr[4];
    uint32_t bKb = ((lane >> 3) & 1) * 16;
    {
        int i = lane & 7;
#pragma unroll
        for (int g = 0; g < 4; g++) {
            int n = 64 * wn + 8 * (2 * g + (lane >> 4)) + i;
            bOff[g] = A_BYTES + n * 128;
            bXr[g]  = (n & 7) * 16;
        }
    }

    float acc[2][8][4];
#pragma unroll
    for (int i = 0; i < 2; i++)
#pragma unroll
        for (int j = 0; j < 8; j++)
#pragma unroll
            for (int k = 0; k < 4; k++) acc[i][j][k] = 0.0f;

    auto load_stage = [&](int s, int kt) {
        uint32_t ad = sb + s * STAGE_BYTES;
        const __half* Ag = A + (size_t)m0 * 512 + kt * 64;
#pragma unroll
        for (int i = 0; i < 4; i++) {            // 256 rows x 128B = 2048 chunks / 512 thr
            int idx = i * 512 + tid;
            int r = idx >> 3, c = idx & 7;
            CPASYNC16(ad + SWZ(r * 128 + c * 16), Ag + (size_t)r * 512 + c * 8);
        }
        uint32_t bd = ad + A_BYTES;
        const __half* Bg = Bt + (size_t)n0 * 512 + kt * 64;
#pragma unroll
        for (int i = 0; i < 2; i++) {            // 128 rows x 128B = 1024 chunks / 512 thr
            int idx = i * 512 + tid;
            int r = idx >> 3, c = idx & 7;
            CPASYNC16(bd + SWZ(r * 128 + c * 16), Bg + (size_t)r * 512 + c * 8);
        }
        CP_COMMIT();
    };

    load_stage(0, 0);
    load_stage(1, 1);
#pragma unroll
    for (int kt = 0; kt < 8; ++kt) {
        if (kt < 7) CP_WAIT1(); else CP_WAIT0();
        __syncthreads();
        if (kt + 2 < 8) load_stage((kt + 2) % 3, kt + 2);

        uint32_t stg = sb + (kt % 3) * STAGE_BYTES;
#pragma unroll
        for (int ks = 0; ks < 4; ks++) {
            uint32_t kbyte = ks * 32;
            uint32_t bfr[8][2];
#pragma unroll
            for (int g = 0; g < 4; g++) {
                uint32_t addr = stg + bOff[g] + ((kbyte + bKb) ^ bXr[g]);
                LDSM4(bfr[2*g][0], bfr[2*g][1], bfr[2*g+1][0], bfr[2*g+1][1], addr);
            }
#pragma unroll
            for (int i = 0; i < 2; i++) {
                uint32_t a0, a1, a2, a3;
                uint32_t addr = stg + aOff[i] + ((kbyte + aKb) ^ aXr[i]);
                LDSM4(a0, a1, a2, a3, addr);
#pragma unroll
                for (int j = 0; j < 8; j++)
                    MMA16816(acc[i][j][0], acc[i][j][1], acc[i][j][2], acc[i][j][3],
                             a0, a1, a2, a3, bfr[j][0], bfr[j][1]);
            }
        }
    }

    // Epilogue: bias (+ fused ELU + per-head L2 norm for q,k), store fp16
    float bv[16];
#pragma unroll
    for (int j = 0; j < 8; j++) {
        int col = n0 + 64 * wn + 8 * j + 2 * tig;
        bv[2*j]   = __ldg(bias + col);
        bv[2*j+1] = __ldg(bias + col + 1);
    }
    bool dof = fuse && (n0 + 64 * wn) < 1024;
#pragma unroll
    for (int i = 0; i < 2; i++) {
#pragma unroll
        for (int hr = 0; hr < 2; hr++) {
            float v[16];
#pragma unroll
            for (int j = 0; j < 8; j++) {
                v[2*j]   = acc[i][j][2*hr]     + bv[2*j];
                v[2*j+1] = acc[i][j][2*hr + 1] + bv[2*j+1];
            }
            if (dof) {
                float ss = 0.0f;
#pragma unroll
                for (int t = 0; t < 16; t++) {
                    v[t] = v[t] > 0.0f ? v[t] : expm1f(v[t]);
                    ss += v[t] * v[t];
                }
                ss += __shfl_xor_sync(0xffffffffu, ss, 1);
                ss += __shfl_xor_sync(0xffffffffu, ss, 2);
                float rn = rsqrtf(ss);
#pragma unroll
                for (int t = 0; t < 16; t++) v[t] *= rn;
            }
            int row = m0 + 32 * wm + 16 * i + 8 * hr + gid;
            __half* cp = (mode == 0)
                ? g_qkv + (size_t)row * 1536 + n0 + 64 * wn + 2 * tig
                : g_oh  + (size_t)row * 512  + n0 + 64 * wn + 2 * tig;
#pragma unroll
            for (int j = 0; j < 8; j++) {
                __half2 hv = __floats2half2_rn(v[2*j], v[2*j+1]);
                *(uint32_t*)(cp + 8 * j) = *(uint32_t*)&hv;
            }
        }
    }
}

// ---------------------------------------------------------------------------
// Fused linear attention per (b,h): KV = kn^T v ; ctx = qn KV / 8  (all HMMA)
//   smem: qn/kn/v [208 x 64] fp16 swizzled (rows 200..207 zero) + KV [64x64] fp16
// ---------------------------------------------------------------------------
#define SP 208
#define T_Q 0
#define T_K (SP * 128)
#define T_V (2 * SP * 128)
#define T_KV (3 * SP * 128)
#define ATTN_SMEM (3 * SP * 128 + 64 * 128)

__global__ void __launch_bounds__(256, 2) fused_attn() {
    extern __shared__ char sm[];
    uint32_t sb = smem_u32(sm);
    int tid = threadIdx.x, warp = tid >> 5, lane = tid & 31;
    int gid = lane >> 2, tig = lane & 3;
    int bh = blockIdx.x;
    int b = bh >> 3, h = bh & 7;

    // ---- load qn, kn, v tiles (200 rows x 64 halves each) ----
    const __half* base = g_qkv + (size_t)b * 200 * 1536 + h * 64;
    for (int i = tid; i < 1600; i += 256) {
        int r = i >> 3, c = i & 7;
        size_t off = (size_t)r * 1536 + c * 8;
        uint32_t sw = SWZ(r * 128 + c * 16);
        CPASYNC16(sb + T_Q + sw, base + off);
        CPASYNC16(sb + T_K + sw, base + 512 + off);
        CPASYNC16(sb + T_V + sw, base + 1024 + off);
    }
    CP_COMMIT();
    // zero pad rows 200..207
    if (tid < 192) {
        int t = tid >> 6, rem = tid & 63;
        int r = 200 + (rem >> 3), c = rem & 7;
        uint32_t sw = SWZ(r * 128 + c * 16);
        uint32_t tb = (t == 0) ? T_Q : (t == 1) ? T_K : T_V;
        *(uint4*)(sm + tb + sw) = make_uint4(0, 0, 0, 0);
    }
    CP_WAIT0();
    __syncthreads();

    // ---- phase 1: KV[d,e] = sum_s kn[s,d] * v[s,e]  (warp grid 4x2, tile 16x32)
    int wm = warp >> 1, wn = warp & 1;
    int d0 = 16 * wm, e0 = 32 * wn;
    float acc1[4][4];
#pragma unroll
    for (int j = 0; j < 4; j++)
#pragma unroll
        for (int k = 0; k < 4; k++) acc1[j][k] = 0.0f;

    int sA_l = (lane & 7) + 8 * (lane >> 4);
    int dA = d0 + 8 * ((lane >> 3) & 1);
    int sB_l = (lane & 7) + 8 * ((lane >> 3) & 1);
    int eB_l = 8 * (lane >> 4);

#pragma unroll
    for (int ks = 0; ks < 13; ks++) {
        int s0 = ks * 16;
        uint32_t a0, a1, a2, a3;
        {
            int sA = s0 + sA_l;
            uint32_t addr = sb + T_K + sA * 128 + ((dA * 2) ^ ((sA & 7) * 16));
            LDSM4T(a0, a1, a2, a3, addr);
        }
        uint32_t bfr[4][2];
#pragma unroll
        for (int g = 0; g < 2; g++) {
            int sB = s0 + sB_l;
            int eB = e0 + 16 * g + eB_l;
            uint32_t addr = sb + T_V + sB * 128 + ((eB * 2) ^ ((sB & 7) * 16));
            LDSM4T(bfr[2*g][0], bfr[2*g][1], bfr[2*g+1][0], bfr[2*g+1][1], addr);
        }
#pragma unroll
        for (int j = 0; j < 4; j++)
            MMA16816(acc1[j][0], acc1[j][1], acc1[j][2], acc1[j][3],
                     a0, a1, a2, a3, bfr[j][0], bfr[j][1]);
    }
    // store KV (fp16, swizzled) to smem
#pragma unroll
    for (int j = 0; j < 4; j++) {
#pragma unroll
        for (int hr = 0; hr < 2; hr++) {
            int row = d0 + 8 * hr + gid;
            int colb = (32 * wn + 8 * j + 2 * tig) * 2;
            __half2 hv = __floats2half2_rn(acc1[j][2*hr], acc1[j][2*hr+1]);
            *(uint32_t*)(sm + T_KV + row * 128 + (colb ^ ((row & 7) * 16))) = *(uint32_t*)&hv;
        }
    }
    __syncthreads();

    // ---- phase 2: ctx[s,e] = (1/8) sum_d qn[s,d] * KV[d,e] ----
    int rA_l = (lane & 7) + 8 * ((lane >> 3) & 1);
    int cA_l = 8 * (lane >> 4);
    int dB_l = (lane & 7) + 8 * ((lane >> 3) & 1);
    int eB2_l = 8 * (lane >> 4);

#pragma unroll
    for (int rep = 0; rep < 2; rep++) {
        int mt = warp + 8 * rep;
        if (mt > 12) break;
        int s0 = mt * 16;
        float acc2[8][4];
#pragma unroll
        for (int j = 0; j < 8; j++)
#pragma unroll
            for (int k = 0; k < 4; k++) acc2[j][k] = 0.0f;

#pragma unroll
        for (int kk = 0; kk < 4; kk++) {
            int kd0 = kk * 16;
            uint32_t a0, a1, a2, a3;
            {
                int r = s0 + rA_l;
                int dc = kd0 + cA_l;
                uint32_t addr = sb + T_Q + r * 128 + ((dc * 2) ^ ((r & 7) * 16));
                LDSM4(a0, a1, a2, a3, addr);
            }
            uint32_t bfr[8][2];
#pragma unroll
            for (int g = 0; g < 4; g++) {
                int dB = kd0 + dB_l;
                int eB = 16 * g + eB2_l;
                uint32_t addr = sb + T_KV + dB * 128 + ((eB * 2) ^ ((dB & 7) * 16));
                LDSM4T(bfr[2*g][0], bfr[2*g][1], bfr[2*g+1][0], bfr[2*g+1][1], addr);
            }
#pragma unroll
            for (int j = 0; j < 8; j++)
                MMA16816(acc2[j][0], acc2[j][1], acc2[j][2], acc2[j][3],
                         a0, a1, a2, a3, bfr[j][0], bfr[j][1]);
        }
        // store ctx rows (guard s < 200)
#pragma unroll
        for (int hr = 0; hr < 2; hr++) {
            int s = s0 + 8 * hr + gid;
            if (s < 200) {
                __half* cp = g_ctxh + ((size_t)b * 200 + s) * 512 + h * 64 + 2 * tig;
#pragma unroll
                for (int j = 0; j < 8; j++) {
                    __half2 hv = __floats2half2_rn(acc2[j][2*hr] * 0.125f,
                                                   acc2[j][2*hr+1] * 0.125f);
                    *(uint32_t*)(cp + 8 * j) = *(uint32_t*)&hv;
                }
            }
        }
    }
}

// ---------------------------------------------------------------------------
// out = LayerNorm(g_oh + g_hh)   (both residual inputs fp16)
// ---------------------------------------------------------------------------
__global__ void final_ln(const float* __restrict__ g, const float* __restrict__ bv_,
                         float* __restrict__ out) {
    size_t row = blockIdx.x;
    int t = threadIdx.x;
    uint2 ou = ((const uint2*)g_oh)[row * 128 + t];
    uint2 hu = ((const uint2*)g_hh)[row * 128 + t];
    float2 o01 = __half22float2(*(__half2*)&ou.x);
    float2 o23 = __half22float2(*(__half2*)&ou.y);
    float2 h01 = __half22float2(*(__half2*)&hu.x);
    float2 h23 = __half22float2(*(__half2*)&hu.y);
    float4 ov;
    ov.x = o01.x + h01.x; ov.y = o01.y + h01.y;
    ov.z = o23.x + h23.x; ov.w = o23.y + h23.y;
    float s  = ov.x + ov.y + ov.z + ov.w;
    float ss = ov.x*ov.x + ov.y*ov.y + ov.z*ov.z + ov.w*ov.w;
    block_reduce2_128(s, ss);
    float mu  = s * (1.0f / 512.0f);
    float var = ss * (1.0f / 512.0f) - mu * mu;
    float rstd = rsqrtf(var + 1e-12f);
    float4 gv = ((const float4*)g)[t];
    float4 bb = ((const float4*)bv_)[t];
    float4 o;
    o.x = (ov.x - mu) * rstd * gv.x + bb.x;
    o.y = (ov.y - mu) * rstd * gv.y + bb.y;
    o.z = (ov.z - mu) * rstd * gv.z + bb.z;
    o.w = (ov.w - mu) * rstd * gv.w + bb.w;
    ((float4*)out)[row * 128 + t] = o;
}

// ---------------------------------------------------------------------------
// Launch
// ---------------------------------------------------------------------------
extern "C" void kernel_launch(void* const* d_in, const int* in_sizes, int n_in,
                              void* d_out, int out_size) {
    const float* input = (const float*)d_in[0];
    const float* pos   = (const float*)d_in[1];
    // d_in[2] = attention_mask (unused by LinMHA)
    const float* Wq = (const float*)d_in[3];
    const float* bq = (const float*)d_in[4];
    const float* Wk = (const float*)d_in[5];
    const float* bk = (const float*)d_in[6];
    const float* Wv = (const float*)d_in[7];
    const float* bv = (const float*)d_in[8];
    const float* Wd = (const float*)d_in[9];
    const float* bd = (const float*)d_in[10];
    const float* lng = (const float*)d_in[11];
    const float* lnb = (const float*)d_in[12];
    float* out = (float*)d_out;

    static bool attr_set = false;
    if (!attr_set) {
        cudaFuncSetAttribute(gemm_f16, cudaFuncAttributeMaxDynamicSharedMemorySize, GEMM_SMEM);
        cudaFuncSetAttribute(fused_attn, cudaFuncAttributeMaxDynamicSharedMemorySize, ATTN_SMEM);
        attr_set = true;
    }

    pack_wt<<<dim3(16, 16, 4), dim3(32, 8)>>>(Wq, Wk, Wv, Wd);
    pack_bias<<<2, 256>>>(bq, bk, bv);
    add_ln<<<MM, 128>>>(input, pos, lng, lnb);
    gemm_f16<<<dim3(12, 400), 512, GEMM_SMEM>>>(0, nullptr);   // QKV + featmap
    fused_attn<<<4096, 256, ATTN_SMEM>>>();                    // kv + ctx
    gemm_f16<<<dim3(4, 400), 512, GEMM_SMEM>>>(1, bd);         // output proj
    final_ln<<<MM, 128>>>(lng, lnb, out);
}

// round 14
// speedup vs baseline: 1.1922x; 1.0874x over previous
#include <cuda_runtime.h>
#include <cuda_fp16.h>
#include <cstdint>

#define BB 512
#define SS 200
#define DD 512
#define HH 8
#define DHH 64
#define MM (BB*SS)          // 102400 rows

// ---------------------------------------------------------------------------
// Scratch (device globals; no allocations anywhere)
// ---------------------------------------------------------------------------
__device__ __half g_hh  [(size_t)MM * DD];        // fp16 LN(x): GEMM A + residual
__device__ __half g_qkv [(size_t)MM * 3 * DD];    // fp16 [M,1536] q|k|v (featmap fused)
__device__ __half g_ctxh[(size_t)MM * DD];        // fp16 ctx for GEMM2 A
__device__ __half g_oh  [(size_t)MM * DD];        // fp16 out-proj result
__device__ __half g_WtQKV[(size_t)3 * DD * DD];   // [1536][512] = W^T fp16
__device__ __half g_WtD  [(size_t)DD * DD];       // [512][512]  = Wd^T fp16
__device__ float  g_bqkv [3 * DD];

// ---------------------------------------------------------------------------
// Helpers
// ---------------------------------------------------------------------------
__device__ __forceinline__ uint32_t smem_u32(const void* p) {
    uint32_t a;
    asm("{ .reg .u64 t; cvta.to.shared.u64 t, %1; cvt.u32.u64 %0, t; }"
        : "=r"(a) : "l"(p));
    return a;
}
#define CPASYNC16(dst, src) \
    asm volatile("cp.async.cg.shared.global [%0], [%1], 16;" :: "r"(dst), "l"(src) : "memory")
#define CP_COMMIT() asm volatile("cp.async.commit_group;" ::: "memory")
#define CP_WAIT0()  asm volatile("cp.async.wait_group 0;" ::: "memory")
#define CP_WAIT1()  asm volatile("cp.async.wait_group 1;" ::: "memory")
#define SWZ(o) ((o) ^ (((o) >> 3) & 0x70))
#define LDSM4(r0, r1, r2, r3, a) \
    asm volatile("ldmatrix.sync.aligned.m8n8.x4.shared.b16 {%0,%1,%2,%3}, [%4];" \
                 : "=r"(r0), "=r"(r1), "=r"(r2), "=r"(r3) : "r"(a))
#define LDSM4T(r0, r1, r2, r3, a) \
    asm volatile("ldmatrix.sync.aligned.m8n8.x4.trans.shared.b16 {%0,%1,%2,%3}, [%4];" \
                 : "=r"(r0), "=r"(r1), "=r"(r2), "=r"(r3) : "r"(a))
#define MMA16816(c0,c1,c2,c3,a0,a1,a2,a3,b0,b1) \
    asm volatile("mma.sync.aligned.m16n8k16.row.col.f32.f16.f16.f32 " \
                 "{%0,%1,%2,%3},{%4,%5,%6,%7},{%8,%9},{%0,%1,%2,%3};" \
                 : "+f"(c0), "+f"(c1), "+f"(c2), "+f"(c3) \
                 : "r"(a0), "r"(a1), "r"(a2), "r"(a3), "r"(b0), "r"(b1))

// ---------------------------------------------------------------------------
// Weight transpose + fp16: Wt[n][k] = fp16(W[k][n]). grid (16,16,4), block (32,8)
// ---------------------------------------------------------------------------
__global__ void pack_wt(const float* __restrict__ Wq, const float* __restrict__ Wk,
                        const float* __restrict__ Wv, const float* __restrict__ Wd) {
    __shared__ float t[32][33];
    int z = blockIdx.z;
    const float* W = z == 0 ? Wq : z == 1 ? Wk : z == 2 ? Wv : Wd;
    int x0 = blockIdx.x * 32, y0 = blockIdx.y * 32;
    int tx = threadIdx.x, ty = threadIdx.y;
#pragma unroll
    for (int i = 0; i < 32; i += 8)
        t[ty + i][tx] = W[(size_t)(y0 + ty + i) * 512 + x0 + tx];
    __syncthreads();
    __half* dst = (z < 3) ? (g_WtQKV + (size_t)z * 512 * 512) : g_WtD;
#pragma unroll
    for (int i = 0; i < 32; i += 8)
        dst[(size_t)(x0 + ty + i) * 512 + y0 + tx] = __float2half_rn(t[tx][ty + i]);
}

__global__ void pack_bias(const float* __restrict__ bq, const float* __restrict__ bk,
                          const float* __restrict__ bv) {
    int i = blockIdx.x * 256 + threadIdx.x;
    if (i < 512) { g_bqkv[i] = bq[i]; g_bqkv[512 + i] = bk[i]; g_bqkv[1024 + i] = bv[i]; }
}

// ---------------------------------------------------------------------------
// Per-128-thread-group reduce (2 groups per 256-thread block, 2 values)
// ---------------------------------------------------------------------------
__device__ __forceinline__ void group_reduce2(float& a, float& b, int grp) {
#pragma unroll
    for (int o = 16; o > 0; o >>= 1) {
        a += __shfl_xor_sync(0xffffffffu, a, o);
        b += __shfl_xor_sync(0xffffffffu, b, o);
    }
    __shared__ float sa[8], sb[8];
    int w = threadIdx.x >> 5, l = threadIdx.x & 31;
    if (l == 0) { sa[w] = a; sb[w] = b; }
    __syncthreads();
    int base = grp * 4;
    a = sa[base] + sa[base + 1] + sa[base + 2] + sa[base + 3];
    b = sb[base] + sb[base + 1] + sb[base + 2] + sb[base + 3];
}

// ---------------------------------------------------------------------------
// h = LayerNorm(input + pos); fp16 out. 2 rows per 256-thread block.
// ---------------------------------------------------------------------------
__global__ void add_ln(const float* __restrict__ x, const float* __restrict__ p,
                       const float* __restrict__ g, const float* __restrict__ b) {
    int grp = threadIdx.x >> 7;
    int t   = threadIdx.x & 127;
    size_t row = (size_t)blockIdx.x * 2 + grp;
    float4 xv = ((const float4*)x)[row * 128 + t];
    float4 pv = ((const float4*)p)[row * 128 + t];
    xv.x += pv.x; xv.y += pv.y; xv.z += pv.z; xv.w += pv.w;
    float s  = xv.x + xv.y + xv.z + xv.w;
    float ss = xv.x*xv.x + xv.y*xv.y + xv.z*xv.z + xv.w*xv.w;
    group_reduce2(s, ss, grp);
    float mu  = s * (1.0f / 512.0f);
    float var = ss * (1.0f / 512.0f) - mu * mu;
    float rstd = rsqrtf(var + 1e-12f);
    float4 gv = ((const float4*)g)[t];
    float4 bv = ((const float4*)b)[t];
    float4 o;
    o.x = (xv.x - mu) * rstd * gv.x + bv.x;
    o.y = (xv.y - mu) * rstd * gv.y + bv.y;
    o.z = (xv.z - mu) * rstd * gv.z + bv.z;
    o.w = (xv.w - mu) * rstd * gv.w + bv.w;
    __half2 h01 = __floats2half2_rn(o.x, o.y);
    __half2 h23 = __floats2half2_rn(o.z, o.w);
    uint2 u; u.x = *(uint32_t*)&h01; u.y = *(uint32_t*)&h23;
    ((uint2*)g_hh)[row * 128 + t] = u;
}

// ---------------------------------------------------------------------------
// fp16 GEMM (mma.sync + ldmatrix, 3-stage cp.async, unrolled kt):
//   C = A[M,512]*Bt^T + bias. Tile 128(M) x 128(N), 8 warps, warp 32x64.
//   mode 0: QKV + featmap -> g_qkv fp16. mode 1: -> g_oh fp16
// ---------------------------------------------------------------------------
#define STAGE_BYTES 32768            // A 16KB + B 16KB
#define GEMM_SMEM   (3 * STAGE_BYTES)

__global__ void __launch_bounds__(256, 2) gemm_f16(int mode, const float* __restrict__ extB) {
    const __half* A; const __half* Bt; const float* bias; int N, fuse;
    if (mode == 0) { A = g_hh;   Bt = g_WtQKV; bias = g_bqkv; N = 1536; fuse = 1; }
    else           { A = g_ctxh; Bt = g_WtD;   bias = extB;   N = 512;  fuse = 0; }

    extern __shared__ char sm[];
    int tid = threadIdx.x, warp = tid >> 5, lane = tid & 31;
    int wm = warp >> 1, wn = warp & 1;
    int gid = lane >> 2, tig = lane & 3;
    int m0 = blockIdx.y * 128, n0 = blockIdx.x * 128;
    uint32_t sb = smem_u32(sm);

    uint32_t aOff[2], aXr[2];
    uint32_t aKb = (lane >> 4) * 16;
    {
        int jlo = (lane >> 3) & 1, i = lane & 7;
#pragma unroll
        for (int ii = 0; ii < 2; ii++) {
            int m = 32 * wm + 16 * ii + jlo * 8 + i;
            aOff[ii] = m * 128;
            aXr[ii]  = (m & 7) * 16;
        }
    }
    uint32_t bOff[4], bXr[4];
    uint32_t bKb = ((lane >> 3) & 1) * 16;
    {
        int i = lane & 7;
#pragma unroll
        for (int g = 0; g < 4; g++) {
            int n = 64 * wn + 8 * (2 * g + (lane >> 4)) + i;
            bOff[g] = 16384 + n * 128;
            bXr[g]  = (n & 7) * 16;
        }
    }

    float acc[2][8][4];
#pragma unroll
    for (int i = 0; i < 2; i++)
#pragma unroll
        for (int j = 0; j < 8; j++)
#pragma unroll
            for (int k = 0; k < 4; k++) acc[i][j][k] = 0.0f;

    auto load_stage = [&](int s, int kt) {
        uint32_t ad = sb + s * STAGE_BYTES;
        const __half* Ag = A + (size_t)m0 * 512 + kt * 64;
#pragma unroll
        for (int i = 0; i < 4; i++) {
            int idx = i * 256 + tid;
            int r = idx >> 3, c = idx & 7;
            CPASYNC16(ad + SWZ(r * 128 + c * 16), Ag + (size_t)r * 512 + c * 8);
        }
        uint32_t bd = ad + 16384;
        const __half* Bg = Bt + (size_t)n0 * 512 + kt * 64;
#pragma unroll
        for (int i = 0; i < 4; i++) {
            int idx = i * 256 + tid;
            int r = idx >> 3, c = idx & 7;
            CPASYNC16(bd + SWZ(r * 128 + c * 16), Bg + (size_t)r * 512 + c * 8);
        }
        CP_COMMIT();
    };

    load_stage(0, 0);
    load_stage(1, 1);
#pragma unroll
    for (int kt = 0; kt < 8; ++kt) {
        if (kt < 7) CP_WAIT1(); else CP_WAIT0();
        __syncthreads();
        if (kt + 2 < 8) load_stage((kt + 2) % 3, kt + 2);

        uint32_t stg = sb + (kt % 3) * STAGE_BYTES;
#pragma unroll
        for (int ks = 0; ks < 4; ks++) {
            uint32_t kbyte = ks * 32;
            uint32_t bfr[8][2];
#pragma unroll
            for (int g = 0; g < 4; g++) {
                uint32_t addr = stg + bOff[g] + ((kbyte + bKb) ^ bXr[g]);
                LDSM4(bfr[2*g][0], bfr[2*g][1], bfr[2*g+1][0], bfr[2*g+1][1], addr);
            }
#pragma unroll
            for (int i = 0; i < 2; i++) {
                uint32_t a0, a1, a2, a3;
                uint32_t addr = stg + aOff[i] + ((kbyte + aKb) ^ aXr[i]);
                LDSM4(a0, a1, a2, a3, addr);
#pragma unroll
                for (int j = 0; j < 8; j++)
                    MMA16816(acc[i][j][0], acc[i][j][1], acc[i][j][2], acc[i][j][3],
                             a0, a1, a2, a3, bfr[j][0], bfr[j][1]);
            }
        }
    }

    // Epilogue: bias (+ fused ELU + per-head L2 norm for q,k), store fp16
    float bv[16];
#pragma unroll
    for (int j = 0; j < 8; j++) {
        int col = n0 + 64 * wn + 8 * j + 2 * tig;
        bv[2*j]   = __ldg(bias + col);
        bv[2*j+1] = __ldg(bias + col + 1);
    }
    bool dof = fuse && (n0 + 64 * wn) < 1024;
#pragma unroll
    for (int i = 0; i < 2; i++) {
#pragma unroll
        for (int hr = 0; hr < 2; hr++) {
            float v[16];
#pragma unroll
            for (int j = 0; j < 8; j++) {
                v[2*j]   = acc[i][j][2*hr]     + bv[2*j];
                v[2*j+1] = acc[i][j][2*hr + 1] + bv[2*j+1];
            }
            if (dof) {
                float ss = 0.0f;
#pragma unroll
                for (int t = 0; t < 16; t++) {
                    v[t] = v[t] > 0.0f ? v[t] : expm1f(v[t]);
                    ss += v[t] * v[t];
                }
                ss += __shfl_xor_sync(0xffffffffu, ss, 1);
                ss += __shfl_xor_sync(0xffffffffu, ss, 2);
                float rn = rsqrtf(ss);
#pragma unroll
                for (int t = 0; t < 16; t++) v[t] *= rn;
            }
            int row = m0 + 32 * wm + 16 * i + 8 * hr + gid;
            __half* cp = (mode == 0)
                ? g_qkv + (size_t)row * 1536 + n0 + 64 * wn + 2 * tig
                : g_oh  + (size_t)row * 512  + n0 + 64 * wn + 2 * tig;
#pragma unroll
            for (int j = 0; j < 8; j++) {
                __half2 hv = __floats2half2_rn(v[2*j], v[2*j+1]);
                *(uint32_t*)(cp + 8 * j) = *(uint32_t*)&hv;
            }
        }
    }
}

// ---------------------------------------------------------------------------
// Fused linear attention per (b,h): KV = kn^T v ; ctx = qn KV / 8  (all HMMA)
//   smem: qn/kn/v [208 x 64] fp16 swizzled (rows 200..207 zero) + KV [64x64] fp16
// ---------------------------------------------------------------------------
#define SP 208
#define T_Q 0
#define T_K (SP * 128)
#define T_V (2 * SP * 128)
#define T_KV (3 * SP * 128)
#define ATTN_SMEM (3 * SP * 128 + 64 * 128)

__global__ void __launch_bounds__(256, 2) fused_attn() {
    extern __shared__ char sm[];
    uint32_t sb = smem_u32(sm);
    int tid = threadIdx.x, warp = tid >> 5, lane = tid & 31;
    int gid = lane >> 2, tig = lane & 3;
    int bh = blockIdx.x;
    int b = bh >> 3, h = bh & 7;

    // ---- load qn, kn, v tiles (200 rows x 64 halves each) ----
    const __half* base = g_qkv + (size_t)b * 200 * 1536 + h * 64;
    for (int i = tid; i < 1600; i += 256) {
        int r = i >> 3, c = i & 7;
        size_t off = (size_t)r * 1536 + c * 8;
        uint32_t sw = SWZ(r * 128 + c * 16);
        CPASYNC16(sb + T_Q + sw, base + off);
        CPASYNC16(sb + T_K + sw, base + 512 + off);
        CPASYNC16(sb + T_V + sw, base + 1024 + off);
    }
    CP_COMMIT();
    // zero pad rows 200..207
    if (tid < 192) {
        int t = tid >> 6, rem = tid & 63;
        int r = 200 + (rem >> 3), c = rem & 7;
        uint32_t sw = SWZ(r * 128 + c * 16);
        uint32_t tb = (t == 0) ? T_Q : (t == 1) ? T_K : T_V;
        *(uint4*)(sm + tb + sw) = make_uint4(0, 0, 0, 0);
    }
    CP_WAIT0();
    __syncthreads();

    // ---- phase 1: KV[d,e] = sum_s kn[s,d] * v[s,e]  (warp grid 4x2, tile 16x32)
    int wm = warp >> 1, wn = warp & 1;
    int d0 = 16 * wm, e0 = 32 * wn;
    float acc1[4][4];
#pragma unroll
    for (int j = 0; j < 4; j++)
#pragma unroll
        for (int k = 0; k < 4; k++) acc1[j][k] = 0.0f;

    int sA_l = (lane & 7) + 8 * (lane >> 4);
    int dA = d0 + 8 * ((lane >> 3) & 1);
    int sB_l = (lane & 7) + 8 * ((lane >> 3) & 1);
    int eB_l = 8 * (lane >> 4);

#pragma unroll
    for (int ks = 0; ks < 13; ks++) {
        int s0 = ks * 16;
        uint32_t a0, a1, a2, a3;
        {
            int sA = s0 + sA_l;
            uint32_t addr = sb + T_K + sA * 128 + ((dA * 2) ^ ((sA & 7) * 16));
            LDSM4T(a0, a1, a2, a3, addr);
        }
        uint32_t bfr[4][2];
#pragma unroll
        for (int g = 0; g < 2; g++) {
            int sB = s0 + sB_l;
            int eB = e0 + 16 * g + eB_l;
            uint32_t addr = sb + T_V + sB * 128 + ((eB * 2) ^ ((sB & 7) * 16));
            LDSM4T(bfr[2*g][0], bfr[2*g][1], bfr[2*g+1][0], bfr[2*g+1][1], addr);
        }
#pragma unroll
        for (int j = 0; j < 4; j++)
            MMA16816(acc1[j][0], acc1[j][1], acc1[j][2], acc1[j][3],
                     a0, a1, a2, a3, bfr[j][0], bfr[j][1]);
    }
    // store KV (fp16, swizzled) to smem
#pragma unroll
    for (int j = 0; j < 4; j++) {
#pragma unroll
        for (int hr = 0; hr < 2; hr++) {
            int row = d0 + 8 * hr + gid;
            int colb = (32 * wn + 8 * j + 2 * tig) * 2;
            __half2 hv = __floats2half2_rn(acc1[j][2*hr], acc1[j][2*hr+1]);
            *(uint32_t*)(sm + T_KV + row * 128 + (colb ^ ((row & 7) * 16))) = *(uint32_t*)&hv;
        }
    }
    __syncthreads();

    // ---- phase 2: ctx[s,e] = (1/8) sum_d qn[s,d] * KV[d,e] ----
    int rA_l = (lane & 7) + 8 * ((lane >> 3) & 1);
    int cA_l = 8 * (lane >> 4);
    int dB_l = (lane & 7) + 8 * ((lane >> 3) & 1);
    int eB2_l = 8 * (lane >> 4);

#pragma unroll
    for (int rep = 0; rep < 2; rep++) {
        int mt = warp + 8 * rep;
        if (mt > 12) break;
        int s0 = mt * 16;
        float acc2[8][4];
#pragma unroll
        for (int j = 0; j < 8; j++)
#pragma unroll
            for (int k = 0; k < 4; k++) acc2[j][k] = 0.0f;

#pragma unroll
        for (int kk = 0; kk < 4; kk++) {
            int kd0 = kk * 16;
            uint32_t a0, a1, a2, a3;
            {
                int r = s0 + rA_l;
                int dc = kd0 + cA_l;
                uint32_t addr = sb + T_Q + r * 128 + ((dc * 2) ^ ((r & 7) * 16));
                LDSM4(a0, a1, a2, a3, addr);
            }
            uint32_t bfr[8][2];
#pragma unroll
            for (int g = 0; g < 4; g++) {
                int dB = kd0 + dB_l;
                int eB = 16 * g + eB2_l;
                uint32_t addr = sb + T_KV + dB * 128 + ((eB * 2) ^ ((dB & 7) * 16));
                LDSM4T(bfr[2*g][0], bfr[2*g][1], bfr[2*g+1][0], bfr[2*g+1][1], addr);
            }
#pragma unroll
            for (int j = 0; j < 8; j++)
                MMA16816(acc2[j][0], acc2[j][1], acc2[j][2], acc2[j][3],
                         a0, a1, a2, a3, bfr[j][0], bfr[j][1]);
        }
        // store ctx rows (guard s < 200)
#pragma unroll
        for (int hr = 0; hr < 2; hr++) {
            int s = s0 + 8 * hr + gid;
            if (s < 200) {
                __half* cp = g_ctxh + ((size_t)b * 200 + s) * 512 + h * 64 + 2 * tig;
#pragma unroll
                for (int j = 0; j < 8; j++) {
                    __half2 hv = __floats2half2_rn(acc2[j][2*hr] * 0.125f,
                                                   acc2[j][2*hr+1] * 0.125f);
                    *(uint32_t*)(cp + 8 * j) = *(uint32_t*)&hv;
                }
            }
        }
    }
}

// ---------------------------------------------------------------------------
// out = LayerNorm(g_oh + g_hh). 2 rows per 256-thread block.
// ---------------------------------------------------------------------------
__global__ void final_ln(const float* __restrict__ g, const float* __restrict__ bv_,
                         float* __restrict__ out) {
    int grp = threadIdx.x >> 7;
    int t   = threadIdx.x & 127;
    size_t row = (size_t)blockIdx.x * 2 + grp;
    uint2 ou = ((const uint2*)g_oh)[row * 128 + t];
    uint2 hu = ((const uint2*)g_hh)[row * 128 + t];
    float2 o01 = __half22float2(*(__half2*)&ou.x);
    float2 o23 = __half22float2(*(__half2*)&ou.y);
    float2 h01 = __half22float2(*(__half2*)&hu.x);
    float2 h23 = __half22float2(*(__half2*)&hu.y);
    float4 ov;
    ov.x = o01.x + h01.x; ov.y = o01.y + h01.y;
    ov.z = o23.x + h23.x; ov.w = o23.y + h23.y;
    float s  = ov.x + ov.y + ov.z + ov.w;
    float ss = ov.x*ov.x + ov.y*ov.y + ov.z*ov.z + ov.w*ov.w;
    group_reduce2(s, ss, grp);
    float mu  = s * (1.0f / 512.0f);
    float var = ss * (1.0f / 512.0f) - mu * mu;
    float rstd = rsqrtf(var + 1e-12f);
    float4 gv = ((const float4*)g)[t];
    float4 bb = ((const float4*)bv_)[t];
    float4 o;
    o.x = (ov.x - mu) * rstd * gv.x + bb.x;
    o.y = (ov.y - mu) * rstd * gv.y + bb.y;
    o.z = (ov.z - mu) * rstd * gv.z + bb.z;
    o.w = (ov.w - mu) * rstd * gv.w + bb.w;
    ((float4*)out)[row * 128 + t] = o;
}

// ---------------------------------------------------------------------------
// Launch
// ---------------------------------------------------------------------------
extern "C" void kernel_launch(void* const* d_in, const int* in_sizes, int n_in,
                              void* d_out, int out_size) {
    const float* input = (const float*)d_in[0];
    const float* pos   = (const float*)d_in[1];
    // d_in[2] = attention_mask (unused by LinMHA)
    const float* Wq = (const float*)d_in[3];
    const float* bq = (const float*)d_in[4];
    const float* Wk = (const float*)d_in[5];
    const float* bk = (const float*)d_in[6];
    const float* Wv = (const float*)d_in[7];
    const float* bv = (const float*)d_in[8];
    const float* Wd = (const float*)d_in[9];
    const float* bd = (const float*)d_in[10];
    const float* lng = (const float*)d_in[11];
    const float* lnb = (const float*)d_in[12];
    float* out = (float*)d_out;

    static bool attr_set = false;
    if (!attr_set) {
        cudaFuncSetAttribute(gemm_f16, cudaFuncAttributeMaxDynamicSharedMemorySize, GEMM_SMEM);
        cudaFuncSetAttribute(fused_attn, cudaFuncAttributeMaxDynamicSharedMemorySize, ATTN_SMEM);
        attr_set = true;
    }

    pack_wt<<<dim3(16, 16, 4), dim3(32, 8)>>>(Wq, Wk, Wv, Wd);
    pack_bias<<<2, 256>>>(bq, bk, bv);
    add_ln<<<MM / 2, 256>>>(input, pos, lng, lnb);
    gemm_f16<<<dim3(12, 800), 256, GEMM_SMEM>>>(0, nullptr);   // QKV + featmap
    fused_attn<<<4096, 256, ATTN_SMEM>>>();                    // kv + ctx
    gemm_f16<<<dim3(4, 800), 256, GEMM_SMEM>>>(1, bd);         // output proj
    final_ln<<<MM / 2, 256>>>(lng, lnb, out);
}

// round 15
// speedup vs baseline: 1.3229x; 1.1097x over previous
#include <cuda_runtime.h>
#include <cuda_fp16.h>
#include <cstdint>

#define BB 512
#define SS 200
#define DD 512
#define HH 8
#define DHH 64
#define MM (BB*SS)          // 102400 rows

// ---------------------------------------------------------------------------
// Scratch (device globals; no allocations anywhere)
// ---------------------------------------------------------------------------
__device__ __half g_hh  [(size_t)MM * DD];        // fp16 LN(x): GEMM A + residual
__device__ __half g_qkv [(size_t)MM * 3 * DD];    // fp16 [M,1536] q|k|v (featmap fused)
__device__ __half g_ctxh[(size_t)MM * DD];        // fp16 ctx for GEMM2 A
__device__ __half g_oh  [(size_t)MM * DD];        // fp16 out-proj result
__device__ __half g_WtQKV[(size_t)3 * DD * DD];   // [1536][512] = W^T fp16
__device__ __half g_WtD  [(size_t)DD * DD];       // [512][512]  = Wd^T fp16
__device__ float  g_bqkv [3 * DD];

// ---------------------------------------------------------------------------
// Helpers
// ---------------------------------------------------------------------------
__device__ __forceinline__ uint32_t smem_u32(const void* p) {
    uint32_t a;
    asm("{ .reg .u64 t; cvta.to.shared.u64 t, %1; cvt.u32.u64 %0, t; }"
        : "=r"(a) : "l"(p));
    return a;
}
#define CPASYNC16(dst, src) \
    asm volatile("cp.async.cg.shared.global [%0], [%1], 16;" :: "r"(dst), "l"(src) : "memory")
#define CP_COMMIT() asm volatile("cp.async.commit_group;" ::: "memory")
#define CP_WAIT0()  asm volatile("cp.async.wait_group 0;" ::: "memory")
#define CP_WAIT1()  asm volatile("cp.async.wait_group 1;" ::: "memory")
#define SWZ(o) ((o) ^ (((o) >> 3) & 0x70))
#define LDSM4(r0, r1, r2, r3, a) \
    asm volatile("ldmatrix.sync.aligned.m8n8.x4.shared.b16 {%0,%1,%2,%3}, [%4];" \
                 : "=r"(r0), "=r"(r1), "=r"(r2), "=r"(r3) : "r"(a))
#define LDSM4T(r0, r1, r2, r3, a) \
    asm volatile("ldmatrix.sync.aligned.m8n8.x4.trans.shared.b16 {%0,%1,%2,%3}, [%4];" \
                 : "=r"(r0), "=r"(r1), "=r"(r2), "=r"(r3) : "r"(a))
#define MMA16816(c0,c1,c2,c3,a0,a1,a2,a3,b0,b1) \
    asm volatile("mma.sync.aligned.m16n8k16.row.col.f32.f16.f16.f32 " \
                 "{%0,%1,%2,%3},{%4,%5,%6,%7},{%8,%9},{%0,%1,%2,%3};" \
                 : "+f"(c0), "+f"(c1), "+f"(c2), "+f"(c3) \
                 : "r"(a0), "r"(a1), "r"(a2), "r"(a3), "r"(b0), "r"(b1))

// ---------------------------------------------------------------------------
// Weight transpose + fp16: Wt[n][k] = fp16(W[k][n]). grid (16,16,4), block (32,8)
// ---------------------------------------------------------------------------
__global__ void pack_wt(const float* __restrict__ Wq, const float* __restrict__ Wk,
                        const float* __restrict__ Wv, const float* __restrict__ Wd) {
    __shared__ float t[32][33];
    int z = blockIdx.z;
    const float* W = z == 0 ? Wq : z == 1 ? Wk : z == 2 ? Wv : Wd;
    int x0 = blockIdx.x * 32, y0 = blockIdx.y * 32;
    int tx = threadIdx.x, ty = threadIdx.y;
#pragma unroll
    for (int i = 0; i < 32; i += 8)
        t[ty + i][tx] = W[(size_t)(y0 + ty + i) * 512 + x0 + tx];
    __syncthreads();
    __half* dst = (z < 3) ? (g_WtQKV + (size_t)z * 512 * 512) : g_WtD;
#pragma unroll
    for (int i = 0; i < 32; i += 8)
        dst[(size_t)(x0 + ty + i) * 512 + y0 + tx] = __float2half_rn(t[tx][ty + i]);
}

__global__ void pack_bias(const float* __restrict__ bq, const float* __restrict__ bk,
                          const float* __restrict__ bv) {
    int i = blockIdx.x * 256 + threadIdx.x;
    if (i < 512) { g_bqkv[i] = bq[i]; g_bqkv[512 + i] = bk[i]; g_bqkv[1024 + i] = bv[i]; }
}

// ---------------------------------------------------------------------------
// Block reduce (128 threads, 2 values)
// ---------------------------------------------------------------------------
__device__ __forceinline__ void block_reduce2_128(float& a, float& b) {
#pragma unroll
    for (int o = 16; o > 0; o >>= 1) {
        a += __shfl_xor_sync(0xffffffffu, a, o);
        b += __shfl_xor_sync(0xffffffffu, b, o);
    }
    __shared__ float sa[4], sb[4];
    int w = threadIdx.x >> 5, l = threadIdx.x & 31;
    if (l == 0) { sa[w] = a; sb[w] = b; }
    __syncthreads();
    a = sa[0] + sa[1] + sa[2] + sa[3];
    b = sb[0] + sb[1] + sb[2] + sb[3];
}

// ---------------------------------------------------------------------------
// h = LayerNorm(input + pos); write fp16 only (GEMM A + residual)
// ---------------------------------------------------------------------------
__global__ void add_ln(const float* __restrict__ x, const float* __restrict__ p,
                       const float* __restrict__ g, const float* __restrict__ b) {
    size_t row = blockIdx.x;
    int t = threadIdx.x;
    float4 xv = ((const float4*)x)[row * 128 + t];
    float4 pv = ((const float4*)p)[row * 128 + t];
    xv.x += pv.x; xv.y += pv.y; xv.z += pv.z; xv.w += pv.w;
    float s  = xv.x + xv.y + xv.z + xv.w;
    float ss = xv.x*xv.x + xv.y*xv.y + xv.z*xv.z + xv.w*xv.w;
    block_reduce2_128(s, ss);
    float mu  = s * (1.0f / 512.0f);
    float var = ss * (1.0f / 512.0f) - mu * mu;
    float rstd = rsqrtf(var + 1e-12f);
    float4 gv = ((const float4*)g)[t];
    float4 bv = ((const float4*)b)[t];
    float4 o;
    o.x = (xv.x - mu) * rstd * gv.x + bv.x;
    o.y = (xv.y - mu) * rstd * gv.y + bv.y;
    o.z = (xv.z - mu) * rstd * gv.z + bv.z;
    o.w = (xv.w - mu) * rstd * gv.w + bv.w;
    __half2 h01 = __floats2half2_rn(o.x, o.y);
    __half2 h23 = __floats2half2_rn(o.z, o.w);
    uint2 u; u.x = *(uint32_t*)&h01; u.y = *(uint32_t*)&h23;
    ((uint2*)g_hh)[row * 128 + t] = u;
}

// ---------------------------------------------------------------------------
// fp16 GEMM (mma.sync + ldmatrix, 3-stage cp.async, unrolled kt):
//   C = A[M,512]*Bt^T + bias. Tile 128(M) x 128(N), 8 warps, warp 32x64.
//   mode 0: QKV + featmap -> g_qkv fp16. mode 1: -> g_oh fp16
// ---------------------------------------------------------------------------
#define STAGE_BYTES 32768            // A 16KB + B 16KB
#define GEMM_SMEM   (3 * STAGE_BYTES)

__global__ void __launch_bounds__(256, 2) gemm_f16(int mode, const float* __restrict__ extB) {
    const __half* A; const __half* Bt; const float* bias; int N, fuse;
    if (mode == 0) { A = g_hh;   Bt = g_WtQKV; bias = g_bqkv; N = 1536; fuse = 1; }
    else           { A = g_ctxh; Bt = g_WtD;   bias = extB;   N = 512;  fuse = 0; }

    extern __shared__ char sm[];
    int tid = threadIdx.x, warp = tid >> 5, lane = tid & 31;
    int wm = warp >> 1, wn = warp & 1;
    int gid = lane >> 2, tig = lane & 3;
    int m0 = blockIdx.y * 128, n0 = blockIdx.x * 128;
    uint32_t sb = smem_u32(sm);

    uint32_t aOff[2], aXr[2];
    uint32_t aKb = (lane >> 4) * 16;
    {
        int jlo = (lane >> 3) & 1, i = lane & 7;
#pragma unroll
        for (int ii = 0; ii < 2; ii++) {
            int m = 32 * wm + 16 * ii + jlo * 8 + i;
            aOff[ii] = m * 128;
            aXr[ii]  = (m & 7) * 16;
        }
    }
    uint32_t bOff[4], bXr[4];
    uint32_t bKb = ((lane >> 3) & 1) * 16;
    {
        int i = lane & 7;
#pragma unroll
        for (int g = 0; g < 4; g++) {
            int n = 64 * wn + 8 * (2 * g + (lane >> 4)) + i;
            bOff[g] = 16384 + n * 128;
            bXr[g]  = (n & 7) * 16;
        }
    }

    float acc[2][8][4];
#pragma unroll
    for (int i = 0; i < 2; i++)
#pragma unroll
        for (int j = 0; j < 8; j++)
#pragma unroll
            for (int k = 0; k < 4; k++) acc[i][j][k] = 0.0f;

    auto load_stage = [&](int s, int kt) {
        uint32_t ad = sb + s * STAGE_BYTES;
        const __half* Ag = A + (size_t)m0 * 512 + kt * 64;
#pragma unroll
        for (int i = 0; i < 4; i++) {
            int idx = i * 256 + tid;
            int r = idx >> 3, c = idx & 7;
            CPASYNC16(ad + SWZ(r * 128 + c * 16), Ag + (size_t)r * 512 + c * 8);
        }
        uint32_t bd = ad + 16384;
        const __half* Bg = Bt + (size_t)n0 * 512 + kt * 64;
#pragma unroll
        for (int i = 0; i < 4; i++) {
            int idx = i * 256 + tid;
            int r = idx >> 3, c = idx & 7;
            CPASYNC16(bd + SWZ(r * 128 + c * 16), Bg + (size_t)r * 512 + c * 8);
        }
        CP_COMMIT();
    };

    load_stage(0, 0);
    load_stage(1, 1);
#pragma unroll
    for (int kt = 0; kt < 8; ++kt) {
        if (kt < 7) CP_WAIT1(); else CP_WAIT0();
        __syncthreads();
        if (kt + 2 < 8) load_stage((kt + 2) % 3, kt + 2);

        uint32_t stg = sb + (kt % 3) * STAGE_BYTES;
#pragma unroll
        for (int ks = 0; ks < 4; ks++) {
            uint32_t kbyte = ks * 32;
            uint32_t bfr[8][2];
#pragma unroll
            for (int g = 0; g < 4; g++) {
                uint32_t addr = stg + bOff[g] + ((kbyte + bKb) ^ bXr[g]);
                LDSM4(bfr[2*g][0], bfr[2*g][1], bfr[2*g+1][0], bfr[2*g+1][1], addr);
            }
#pragma unroll
            for (int i = 0; i < 2; i++) {
                uint32_t a0, a1, a2, a3;
                uint32_t addr = stg + aOff[i] + ((kbyte + aKb) ^ aXr[i]);
                LDSM4(a0, a1, a2, a3, addr);
#pragma unroll
                for (int j = 0; j < 8; j++)
                    MMA16816(acc[i][j][0], acc[i][j][1], acc[i][j][2], acc[i][j][3],
                             a0, a1, a2, a3, bfr[j][0], bfr[j][1]);
            }
        }
    }

    // Epilogue: bias (+ fused fast-ELU + per-head L2 norm for q,k), store fp16
    float bv[16];
#pragma unroll
    for (int j = 0; j < 8; j++) {
        int col = n0 + 64 * wn + 8 * j + 2 * tig;
        bv[2*j]   = __ldg(bias + col);
        bv[2*j+1] = __ldg(bias + col + 1);
    }
    bool dof = fuse && (n0 + 64 * wn) < 1024;
#pragma unroll
    for (int i = 0; i < 2; i++) {
#pragma unroll
        for (int hr = 0; hr < 2; hr++) {
            float v[16];
#pragma unroll
            for (int j = 0; j < 8; j++) {
                v[2*j]   = acc[i][j][2*hr]     + bv[2*j];
                v[2*j+1] = acc[i][j][2*hr + 1] + bv[2*j+1];
            }
            if (dof) {
                float ss = 0.0f;
#pragma unroll
                for (int t = 0; t < 16; t++) {
                    v[t] = v[t] > 0.0f ? v[t] : (__expf(v[t]) - 1.0f);
                    ss += v[t] * v[t];
                }
                ss += __shfl_xor_sync(0xffffffffu, ss, 1);
                ss += __shfl_xor_sync(0xffffffffu, ss, 2);
                float rn = rsqrtf(ss);
#pragma unroll
                for (int t = 0; t < 16; t++) v[t] *= rn;
            }
            int row = m0 + 32 * wm + 16 * i + 8 * hr + gid;
            __half* cp = (mode == 0)
                ? g_qkv + (size_t)row * 1536 + n0 + 64 * wn + 2 * tig
                : g_oh  + (size_t)row * 512  + n0 + 64 * wn + 2 * tig;
#pragma unroll
            for (int j = 0; j < 8; j++) {
                __half2 hv = __floats2half2_rn(v[2*j], v[2*j+1]);
                *(uint32_t*)(cp + 8 * j) = *(uint32_t*)&hv;
            }
        }
    }
}

// ---------------------------------------------------------------------------
// Fused linear attention per (b,h): KV = kn^T v ; ctx = qn KV / 8  (all HMMA)
//   smem: qn/kn/v [208 x 64] fp16 swizzled (rows 200..207 zero) + KV [64x64] fp16
// ---------------------------------------------------------------------------
#define SP 208
#define T_Q 0
#define T_K (SP * 128)
#define T_V (2 * SP * 128)
#define T_KV (3 * SP * 128)
#define ATTN_SMEM (3 * SP * 128 + 64 * 128)

__global__ void __launch_bounds__(256, 2) fused_attn() {
    extern __shared__ char sm[];
    uint32_t sb = smem_u32(sm);
    int tid = threadIdx.x, warp = tid >> 5, lane = tid & 31;
    int gid = lane >> 2, tig = lane & 3;
    int bh = blockIdx.x;
    int b = bh >> 3, h = bh & 7;

    // ---- load qn, kn, v tiles (200 rows x 64 halves each) ----
    const __half* base = g_qkv + (size_t)b * 200 * 1536 + h * 64;
    for (int i = tid; i < 1600; i += 256) {
        int r = i >> 3, c = i & 7;
        size_t off = (size_t)r * 1536 + c * 8;
        uint32_t sw = SWZ(r * 128 + c * 16);
        CPASYNC16(sb + T_Q + sw, base + off);
        CPASYNC16(sb + T_K + sw, base + 512 + off);
        CPASYNC16(sb + T_V + sw, base + 1024 + off);
    }
    CP_COMMIT();
    // zero pad rows 200..207
    if (tid < 192) {
        int t = tid >> 6, rem = tid & 63;
        int r = 200 + (rem >> 3), c = rem & 7;
        uint32_t sw = SWZ(r * 128 + c * 16);
        uint32_t tb = (t == 0) ? T_Q : (t == 1) ? T_K : T_V;
        *(uint4*)(sm + tb + sw) = make_uint4(0, 0, 0, 0);
    }
    CP_WAIT0();
    __syncthreads();

    // ---- phase 1: KV[d,e] = sum_s kn[s,d] * v[s,e]  (warp grid 4x2, tile 16x32)
    int wm = warp >> 1, wn = warp & 1;
    int d0 = 16 * wm, e0 = 32 * wn;
    float acc1[4][4];
#pragma unroll
    for (int j = 0; j < 4; j++)
#pragma unroll
        for (int k = 0; k < 4; k++) acc1[j][k] = 0.0f;

    int sA_l = (lane & 7) + 8 * (lane >> 4);
    int dA = d0 + 8 * ((lane >> 3) & 1);
    int sB_l = (lane & 7) + 8 * ((lane >> 3) & 1);
    int eB_l = 8 * (lane >> 4);

#pragma unroll
    for (int ks = 0; ks < 13; ks++) {
        int s0 = ks * 16;
        uint32_t a0, a1, a2, a3;
        {
            int sA = s0 + sA_l;
            uint32_t addr = sb + T_K + sA * 128 + ((dA * 2) ^ ((sA & 7) * 16));
            LDSM4T(a0, a1, a2, a3, addr);
        }
        uint32_t bfr[4][2];
#pragma unroll
        for (int g = 0; g < 2; g++) {
            int sB = s0 + sB_l;
            int eB = e0 + 16 * g + eB_l;
            uint32_t addr = sb + T_V + sB * 128 + ((eB * 2) ^ ((sB & 7) * 16));
            LDSM4T(bfr[2*g][0], bfr[2*g][1], bfr[2*g+1][0], bfr[2*g+1][1], addr);
        }
#pragma unroll
        for (int j = 0; j < 4; j++)
            MMA16816(acc1[j][0], acc1[j][1], acc1[j][2], acc1[j][3],
                     a0, a1, a2, a3, bfr[j][0], bfr[j][1]);
    }
    // store KV (fp16, swizzled) to smem
#pragma unroll
    for (int j = 0; j < 4; j++) {
#pragma unroll
        for (int hr = 0; hr < 2; hr++) {
            int row = d0 + 8 * hr + gid;
            int colb = (32 * wn + 8 * j + 2 * tig) * 2;
            __half2 hv = __floats2half2_rn(acc1[j][2*hr], acc1[j][2*hr+1]);
            *(uint32_t*)(sm + T_KV + row * 128 + (colb ^ ((row & 7) * 16))) = *(uint32_t*)&hv;
        }
    }
    __syncthreads();

    // ---- phase 2: ctx[s,e] = (1/8) sum_d qn[s,d] * KV[d,e] ----
    int rA_l = (lane & 7) + 8 * ((lane >> 3) & 1);
    int cA_l = 8 * (lane >> 4);
    int dB_l = (lane & 7) + 8 * ((lane >> 3) & 1);
    int eB2_l = 8 * (lane >> 4);

#pragma unroll
    for (int rep = 0; rep < 2; rep++) {
        int mt = warp + 8 * rep;
        if (mt > 12) break;
        int s0 = mt * 16;
        float acc2[8][4];
#pragma unroll
        for (int j = 0; j < 8; j++)
#pragma unroll
            for (int k = 0; k < 4; k++) acc2[j][k] = 0.0f;

#pragma unroll
        for (int kk = 0; kk < 4; kk++) {
            int kd0 = kk * 16;
            uint32_t a0, a1, a2, a3;
            {
                int r = s0 + rA_l;
                int dc = kd0 + cA_l;
                uint32_t addr = sb + T_Q + r * 128 + ((dc * 2) ^ ((r & 7) * 16));
                LDSM4(a0, a1, a2, a3, addr);
            }
            uint32_t bfr[8][2];
#pragma unroll
            for (int g = 0; g < 4; g++) {
                int dB = kd0 + dB_l;
                int eB = 16 * g + eB2_l;
                uint32_t addr = sb + T_KV + dB * 128 + ((eB * 2) ^ ((dB & 7) * 16));
                LDSM4T(bfr[2*g][0], bfr[2*g][1], bfr[2*g+1][0], bfr[2*g+1][1], addr);
            }
#pragma unroll
            for (int j = 0; j < 8; j++)
                MMA16816(acc2[j][0], acc2[j][1], acc2[j][2], acc2[j][3],
                         a0, a1, a2, a3, bfr[j][0], bfr[j][1]);
        }
        // store ctx rows (guard s < 200)
#pragma unroll
        for (int hr = 0; hr < 2; hr++) {
            int s = s0 + 8 * hr + gid;
            if (s < 200) {
                __half* cp = g_ctxh + ((size_t)b * 200 + s) * 512 + h * 64 + 2 * tig;
#pragma unroll
                for (int j = 0; j < 8; j++) {
                    __half2 hv = __floats2half2_rn(acc2[j][2*hr] * 0.125f,
                                                   acc2[j][2*hr+1] * 0.125f);
                    *(uint32_t*)(cp + 8 * j) = *(uint32_t*)&hv;
                }
            }
        }
    }
}

// ---------------------------------------------------------------------------
// out = LayerNorm(g_oh + g_hh)   (both residual inputs fp16)
// ---------------------------------------------------------------------------
__global__ void final_ln(const float* __restrict__ g, const float* __restrict__ bv_,
                         float* __restrict__ out) {
    size_t row = blockIdx.x;
    int t = threadIdx.x;
    uint2 ou = ((const uint2*)g_oh)[row * 128 + t];
    uint2 hu = ((const uint2*)g_hh)[row * 128 + t];
    float2 o01 = __half22float2(*(__half2*)&ou.x);
    float2 o23 = __half22float2(*(__half2*)&ou.y);
    float2 h01 = __half22float2(*(__half2*)&hu.x);
    float2 h23 = __half22float2(*(__half2*)&hu.y);
    float4 ov;
    ov.x = o01.x + h01.x; ov.y = o01.y + h01.y;
    ov.z = o23.x + h23.x; ov.w = o23.y + h23.y;
    float s  = ov.x + ov.y + ov.z + ov.w;
    float ss = ov.x*ov.x + ov.y*ov.y + ov.z*ov.z + ov.w*ov.w;
    block_reduce2_128(s, ss);
    float mu  = s * (1.0f / 512.0f);
    float var = ss * (1.0f / 512.0f) - mu * mu;
    float rstd = rsqrtf(var + 1e-12f);
    float4 gv = ((const float4*)g)[t];
    float4 bb = ((const float4*)bv_)[t];
    float4 o;
    o.x = (ov.x - mu) * rstd * gv.x + bb.x;
    o.y = (ov.y - mu) * rstd * gv.y + bb.y;
    o.z = (ov.z - mu) * rstd * gv.z + bb.z;
    o.w = (ov.w - mu) * rstd * gv.w + bb.w;
    ((float4*)out)[row * 128 + t] = o;
}

// ---------------------------------------------------------------------------
// Launch
// ---------------------------------------------------------------------------
extern "C" void kernel_launch(void* const* d_in, const int* in_sizes, int n_in,
                              void* d_out, int out_size) {
    const float* input = (const float*)d_in[0];
    const float* pos   = (const float*)d_in[1];
    // d_in[2] = attention_mask (unused by LinMHA)
    const float* Wq = (const float*)d_in[3];
    const float* bq = (const float*)d_in[4];
    const float* Wk = (const float*)d_in[5];
    const float* bk = (const float*)d_in[6];
    const float* Wv = (const float*)d_in[7];
    const float* bv = (const float*)d_in[8];
    const float* Wd = (const float*)d_in[9];
    const float* bd = (const float*)d_in[10];
    const float* lng = (const float*)d_in[11];
    const float* lnb = (const float*)d_in[12];
    float* out = (float*)d_out;

    static bool attr_set = false;
    if (!attr_set) {
        cudaFuncSetAttribute(gemm_f16, cudaFuncAttributeMaxDynamicSharedMemorySize, GEMM_SMEM);
        cudaFuncSetAttribute(fused_attn, cudaFuncAttributeMaxDynamicSharedMemorySize, ATTN_SMEM);
        attr_set = true;
    }

    pack_wt<<<dim3(16, 16, 4), dim3(32, 8)>>>(Wq, Wk, Wv, Wd);
    pack_bias<<<2, 256>>>(bq, bk, bv);
    add_ln<<<MM, 128>>>(input, pos, lng, lnb);
    gemm_f16<<<dim3(12, 800), 256, GEMM_SMEM>>>(0, nullptr);   // QKV + featmap
    fused_attn<<<4096, 256, ATTN_SMEM>>>();                    // kv + ctx
    gemm_f16<<<dim3(4, 800), 256, GEMM_SMEM>>>(1, bd);         // output proj
    final_ln<<<MM, 128>>>(lng, lnb, out);
}

// round 17
// speedup vs baseline: 1.3240x; 1.0008x over previous
#include <cuda_runtime.h>
#include <cuda_fp16.h>
#include <cstdint>

#define BB 512
#define SS 200
#define DD 512
#define HH 8
#define DHH 64
#define MM (BB*SS)          // 102400 rows

// ---------------------------------------------------------------------------
// Scratch (device globals; no allocations anywhere)
// ---------------------------------------------------------------------------
__device__ __half g_hh  [(size_t)MM * DD];        // fp16 LN(x): GEMM A + residual
__device__ __half g_qkv [(size_t)MM * 3 * DD];    // fp16 [M,1536] q|k|v (featmap fused)
__device__ __half g_ctxh[(size_t)MM * DD];        // fp16 ctx for GEMM2 A
__device__ __half g_oh  [(size_t)MM * DD];        // fp16 out-proj result
__device__ __half g_WtQKV[(size_t)3 * DD * DD];   // [1536][512] = W^T fp16
__device__ __half g_WtD  [(size_t)DD * DD];       // [512][512]  = Wd^T fp16
__device__ float  g_bqkv [3 * DD];

// ---------------------------------------------------------------------------
// Helpers
// ---------------------------------------------------------------------------
__device__ __forceinline__ uint32_t smem_u32(const void* p) {
    uint32_t a;
    asm("{ .reg .u64 t; cvta.to.shared.u64 t, %1; cvt.u32.u64 %0, t; }"
        : "=r"(a) : "l"(p));
    return a;
}
#define CPASYNC16(dst, src) \
    asm volatile("cp.async.cg.shared.global [%0], [%1], 16;" :: "r"(dst), "l"(src) : "memory")
#define CP_COMMIT() asm volatile("cp.async.commit_group;" ::: "memory")
#define CP_WAIT0()  asm volatile("cp.async.wait_group 0;" ::: "memory")
#define CP_WAIT1()  asm volatile("cp.async.wait_group 1;" ::: "memory")
#define SWZ(o) ((o) ^ (((o) >> 3) & 0x70))
#define LDSM4(r0, r1, r2, r3, a) \
    asm volatile("ldmatrix.sync.aligned.m8n8.x4.shared.b16 {%0,%1,%2,%3}, [%4];" \
                 : "=r"(r0), "=r"(r1), "=r"(r2), "=r"(r3) : "r"(a))
#define LDSM4T(r0, r1, r2, r3, a) \
    asm volatile("ldmatrix.sync.aligned.m8n8.x4.trans.shared.b16 {%0,%1,%2,%3}, [%4];" \
                 : "=r"(r0), "=r"(r1), "=r"(r2), "=r"(r3) : "r"(a))
#define MMA16816(c0,c1,c2,c3,a0,a1,a2,a3,b0,b1) \
    asm volatile("mma.sync.aligned.m16n8k16.row.col.f32.f16.f16.f32 " \
                 "{%0,%1,%2,%3},{%4,%5,%6,%7},{%8,%9},{%0,%1,%2,%3};" \
                 : "+f"(c0), "+f"(c1), "+f"(c2), "+f"(c3) \
                 : "r"(a0), "r"(a1), "r"(a2), "r"(a3), "r"(b0), "r"(b1))

// ---------------------------------------------------------------------------
// Weight transpose + fp16: Wt[n][k] = fp16(W[k][n]). grid (16,16,4), block (32,8)
// ---------------------------------------------------------------------------
__global__ void pack_wt(const float* __restrict__ Wq, const float* __restrict__ Wk,
                        const float* __restrict__ Wv, const float* __restrict__ Wd) {
    __shared__ float t[32][33];
    int z = blockIdx.z;
    const float* W = z == 0 ? Wq : z == 1 ? Wk : z == 2 ? Wv : Wd;
    int x0 = blockIdx.x * 32, y0 = blockIdx.y * 32;
    int tx = threadIdx.x, ty = threadIdx.y;
#pragma unroll
    for (int i = 0; i < 32; i += 8)
        t[ty + i][tx] = W[(size_t)(y0 + ty + i) * 512 + x0 + tx];
    __syncthreads();
    __half* dst = (z < 3) ? (g_WtQKV + (size_t)z * 512 * 512) : g_WtD;
#pragma unroll
    for (int i = 0; i < 32; i += 8)
        dst[(size_t)(x0 + ty + i) * 512 + y0 + tx] = __float2half_rn(t[tx][ty + i]);
}

__global__ void pack_bias(const float* __restrict__ bq, const float* __restrict__ bk,
                          const float* __restrict__ bv) {
    int i = blockIdx.x * 256 + threadIdx.x;
    if (i < 512) { g_bqkv[i] = bq[i]; g_bqkv[512 + i] = bk[i]; g_bqkv[1024 + i] = bv[i]; }
}

// ---------------------------------------------------------------------------
// Block reduce (128 threads, 2 values)
// ---------------------------------------------------------------------------
__device__ __forceinline__ void block_reduce2_128(float& a, float& b) {
#pragma unroll
    for (int o = 16; o > 0; o >>= 1) {
        a += __shfl_xor_sync(0xffffffffu, a, o);
        b += __shfl_xor_sync(0xffffffffu, b, o);
    }
    __shared__ float sa[4], sb[4];
    int w = threadIdx.x >> 5, l = threadIdx.x & 31;
    if (l == 0) { sa[w] = a; sb[w] = b; }
    __syncthreads();
    a = sa[0] + sa[1] + sa[2] + sa[3];
    b = sb[0] + sb[1] + sb[2] + sb[3];
}

// ---------------------------------------------------------------------------
// h = LayerNorm(input + pos); write fp16 only (GEMM A + residual)
// ---------------------------------------------------------------------------
__global__ void add_ln(const float* __restrict__ x, const float* __restrict__ p,
                       const float* __restrict__ g, const float* __restrict__ b) {
    size_t row = blockIdx.x;
    int t = threadIdx.x;
    float4 xv = ((const float4*)x)[row * 128 + t];
    float4 pv = ((const float4*)p)[row * 128 + t];
    xv.x += pv.x; xv.y += pv.y; xv.z += pv.z; xv.w += pv.w;
    float s  = xv.x + xv.y + xv.z + xv.w;
    float ss = xv.x*xv.x + xv.y*xv.y + xv.z*xv.z + xv.w*xv.w;
    block_reduce2_128(s, ss);
    float mu  = s * (1.0f / 512.0f);
    float var = ss * (1.0f / 512.0f) - mu * mu;
    float rstd = rsqrtf(var + 1e-12f);
    float4 gv = ((const float4*)g)[t];
    float4 bv = ((const float4*)b)[t];
    float4 o;
    o.x = (xv.x - mu) * rstd * gv.x + bv.x;
    o.y = (xv.y - mu) * rstd * gv.y + bv.y;
    o.z = (xv.z - mu) * rstd * gv.z + bv.z;
    o.w = (xv.w - mu) * rstd * gv.w + bv.w;
    __half2 h01 = __floats2half2_rn(o.x, o.y);
    __half2 h23 = __floats2half2_rn(o.z, o.w);
    uint2 u; u.x = *(uint32_t*)&h01; u.y = *(uint32_t*)&h23;
    ((uint2*)g_hh)[row * 128 + t] = u;
}

// ---------------------------------------------------------------------------
// fp16 GEMM (mma.sync + ldmatrix, 3-stage cp.async, unrolled kt):
//   C = A[M,512]*Bt^T + bias. Tile 128(M) x 128(N), 8 warps, warp 32x64.
//   mode 0: QKV + featmap -> g_qkv fp16. mode 1: -> g_oh fp16
// ---------------------------------------------------------------------------
#define STAGE_BYTES 32768            // A 16KB + B 16KB
#define GEMM_SMEM   (3 * STAGE_BYTES)

__global__ void __launch_bounds__(256, 2) gemm_f16(int mode, const float* __restrict__ extB) {
    const __half* A; const __half* Bt; const float* bias; int N, fuse;
    if (mode == 0) { A = g_hh;   Bt = g_WtQKV; bias = g_bqkv; N = 1536; fuse = 1; }
    else           { A = g_ctxh; Bt = g_WtD;   bias = extB;   N = 512;  fuse = 0; }

    extern __shared__ char sm[];
    int tid = threadIdx.x, warp = tid >> 5, lane = tid & 31;
    int wm = warp >> 1, wn = warp & 1;
    int gid = lane >> 2, tig = lane & 3;
    int m0 = blockIdx.y * 128, n0 = blockIdx.x * 128;
    uint32_t sb = smem_u32(sm);

    uint32_t aOff[2], aXr[2];
    uint32_t aKb = (lane >> 4) * 16;
    {
        int jlo = (lane >> 3) & 1, i = lane & 7;
#pragma unroll
        for (int ii = 0; ii < 2; ii++) {
            int m = 32 * wm + 16 * ii + jlo * 8 + i;
            aOff[ii] = m * 128;
            aXr[ii]  = (m & 7) * 16;
        }
    }
    uint32_t bOff[4], bXr[4];
    uint32_t bKb = ((lane >> 3) & 1) * 16;
    {
        int i = lane & 7;
#pragma unroll
        for (int g = 0; g < 4; g++) {
            int n = 64 * wn + 8 * (2 * g + (lane >> 4)) + i;
            bOff[g] = 16384 + n * 128;
            bXr[g]  = (n & 7) * 16;
        }
    }

    float acc[2][8][4];
#pragma unroll
    for (int i = 0; i < 2; i++)
#pragma unroll
        for (int j = 0; j < 8; j++)
#pragma unroll
            for (int k = 0; k < 4; k++) acc[i][j][k] = 0.0f;

    auto load_stage = [&](int s, int kt) {
        uint32_t ad = sb + s * STAGE_BYTES;
        const __half* Ag = A + (size_t)m0 * 512 + kt * 64;
#pragma unroll
        for (int i = 0; i < 4; i++) {
            int idx = i * 256 + tid;
            int r = idx >> 3, c = idx & 7;
            CPASYNC16(ad + SWZ(r * 128 + c * 16), Ag + (size_t)r * 512 + c * 8);
        }
        uint32_t bd = ad + 16384;
        const __half* Bg = Bt + (size_t)n0 * 512 + kt * 64;
#pragma unroll
        for (int i = 0; i < 4; i++) {
            int idx = i * 256 + tid;
            int r = idx >> 3, c = idx & 7;
            CPASYNC16(bd + SWZ(r * 128 + c * 16), Bg + (size_t)r * 512 + c * 8);
        }
        CP_COMMIT();
    };

    load_stage(0, 0);
    load_stage(1, 1);
#pragma unroll
    for (int kt = 0; kt < 8; ++kt) {
        if (kt < 7) CP_WAIT1(); else CP_WAIT0();
        __syncthreads();
        if (kt + 2 < 8) load_stage((kt + 2) % 3, kt + 2);

        uint32_t stg = sb + (kt % 3) * STAGE_BYTES;
#pragma unroll
        for (int ks = 0; ks < 4; ks++) {
            uint32_t kbyte = ks * 32;
            uint32_t bfr[8][2];
#pragma unroll
            for (int g = 0; g < 4; g++) {
                uint32_t addr = stg + bOff[g] + ((kbyte + bKb) ^ bXr[g]);
                LDSM4(bfr[2*g][0], bfr[2*g][1], bfr[2*g+1][0], bfr[2*g+1][1], addr);
            }
#pragma unroll
            for (int i = 0; i < 2; i++) {
                uint32_t a0, a1, a2, a3;
                uint32_t addr = stg + aOff[i] + ((kbyte + aKb) ^ aXr[i]);
                LDSM4(a0, a1, a2, a3, addr);
#pragma unroll
                for (int j = 0; j < 8; j++)
                    MMA16816(acc[i][j][0], acc[i][j][1], acc[i][j][2], acc[i][j][3],
                             a0, a1, a2, a3, bfr[j][0], bfr[j][1]);
            }
        }
    }

    // Epilogue: bias (+ fused fast-ELU + per-head L2 norm for q,k), store fp16
    float bv[16];
#pragma unroll
    for (int j = 0; j < 8; j++) {
        int col = n0 + 64 * wn + 8 * j + 2 * tig;
        bv[2*j]   = __ldg(bias + col);
        bv[2*j+1] = __ldg(bias + col + 1);
    }
    bool dof = fuse && (n0 + 64 * wn) < 1024;
#pragma unroll
    for (int i = 0; i < 2; i++) {
#pragma unroll
        for (int hr = 0; hr < 2; hr++) {
            float v[16];
#pragma unroll
            for (int j = 0; j < 8; j++) {
                v[2*j]   = acc[i][j][2*hr]     + bv[2*j];
                v[2*j+1] = acc[i][j][2*hr + 1] + bv[2*j+1];
            }
            if (dof) {
                float ss = 0.0f;
#pragma unroll
                for (int t = 0; t < 16; t++) {
                    v[t] = v[t] > 0.0f ? v[t] : (__expf(v[t]) - 1.0f);
                    ss += v[t] * v[t];
                }
                ss += __shfl_xor_sync(0xffffffffu, ss, 1);
                ss += __shfl_xor_sync(0xffffffffu, ss, 2);
                float rn = rsqrtf(ss);
#pragma unroll
                for (int t = 0; t < 16; t++) v[t] *= rn;
            }
            int row = m0 + 32 * wm + 16 * i + 8 * hr + gid;
            __half* cp = (mode == 0)
                ? g_qkv + (size_t)row * 1536 + n0 + 64 * wn + 2 * tig
                : g_oh  + (size_t)row * 512  + n0 + 64 * wn + 2 * tig;
#pragma unroll
            for (int j = 0; j < 8; j++) {
                __half2 hv = __floats2half2_rn(v[2*j], v[2*j+1]);
                *(uint32_t*)(cp + 8 * j) = *(uint32_t*)&hv;
            }
        }
    }
}

// ---------------------------------------------------------------------------
// Fused linear attention per (b,h): KV = kn^T v ; ctx = qn KV / 8  (all HMMA)
//   smem: qn/kn/v [208 x 64] fp16 swizzled (rows 200..207 zero) + KV [64x64] fp16
//   K,V committed first (group A); Q second (group B) -> Q load overlaps phase 1.
// ---------------------------------------------------------------------------
#define SP 208
#define T_Q 0
#define T_K (SP * 128)
#define T_V (2 * SP * 128)
#define T_KV (3 * SP * 128)
#define ATTN_SMEM (3 * SP * 128 + 64 * 128)

__global__ void __launch_bounds__(256, 2) fused_attn() {
    extern __shared__ char sm[];
    uint32_t sb = smem_u32(sm);
    int tid = threadIdx.x, warp = tid >> 5, lane = tid & 31;
    int gid = lane >> 2, tig = lane & 3;
    int bh = blockIdx.x;
    int b = bh >> 3, h = bh & 7;

    // ---- group A: K and V (needed for phase 1) ----
    const __half* base = g_qkv + (size_t)b * 200 * 1536 + h * 64;
    for (int i = tid; i < 1600; i += 256) {
        int r = i >> 3, c = i & 7;
        size_t off = (size_t)r * 1536 + c * 8;
        uint32_t sw = SWZ(r * 128 + c * 16);
        CPASYNC16(sb + T_K + sw, base + 512 + off);
        CPASYNC16(sb + T_V + sw, base + 1024 + off);
    }
    CP_COMMIT();
    // ---- group B: Q (needed only for phase 2) ----
    for (int i = tid; i < 1600; i += 256) {
        int r = i >> 3, c = i & 7;
        size_t off = (size_t)r * 1536 + c * 8;
        uint32_t sw = SWZ(r * 128 + c * 16);
        CPASYNC16(sb + T_Q + sw, base + off);
    }
    CP_COMMIT();
    // zero pad rows 200..207 (never touched by cp.async)
    if (tid < 192) {
        int t = tid >> 6, rem = tid & 63;
        int r = 200 + (rem >> 3), c = rem & 7;
        uint32_t sw = SWZ(r * 128 + c * 16);
        uint32_t tb = (t == 0) ? T_Q : (t == 1) ? T_K : T_V;
        *(uint4*)(sm + tb + sw) = make_uint4(0, 0, 0, 0);
    }
    CP_WAIT1();                    // K,V resident; Q still in flight
    __syncthreads();

    // ---- phase 1: KV[d,e] = sum_s kn[s,d] * v[s,e]  (warp grid 4x2, tile 16x32)
    int wm = warp >> 1, wn = warp & 1;
    int d0 = 16 * wm, e0 = 32 * wn;
    float acc1[4][4];
#pragma unroll
    for (int j = 0; j < 4; j++)
#pragma unroll
        for (int k = 0; k < 4; k++) acc1[j][k] = 0.0f;

    int sA_l = (lane & 7) + 8 * (lane >> 4);
    int dA = d0 + 8 * ((lane >> 3) & 1);
    int sB_l = (lane & 7) + 8 * ((lane >> 3) & 1);
    int eB_l = 8 * (lane >> 4);

#pragma unroll
    for (int ks = 0; ks < 13; ks++) {
        int s0 = ks * 16;
        uint32_t a0, a1, a2, a3;
        {
            int sA = s0 + sA_l;
            uint32_t addr = sb + T_K + sA * 128 + ((dA * 2) ^ ((sA & 7) * 16));
            LDSM4T(a0, a1, a2, a3, addr);
        }
        uint32_t bfr[4][2];
#pragma unroll
        for (int g = 0; g < 2; g++) {
            int sB = s0 + sB_l;
            int eB = e0 + 16 * g + eB_l;
            uint32_t addr = sb + T_V + sB * 128 + ((eB * 2) ^ ((sB & 7) * 16));
            LDSM4T(bfr[2*g][0], bfr[2*g][1], bfr[2*g+1][0], bfr[2*g+1][1], addr);
        }
#pragma unroll
        for (int j = 0; j < 4; j++)
            MMA16816(acc1[j][0], acc1[j][1], acc1[j][2], acc1[j][3],
                     a0, a1, a2, a3, bfr[j][0], bfr[j][1]);
    }
    // store KV (fp16, swizzled) to smem
#pragma unroll
    for (int j = 0; j < 4; j++) {
#pragma unroll
        for (int hr = 0; hr < 2; hr++) {
            int row = d0 + 8 * hr + gid;
            int colb = (32 * wn + 8 * j + 2 * tig) * 2;
            __half2 hv = __floats2half2_rn(acc1[j][2*hr], acc1[j][2*hr+1]);
            *(uint32_t*)(sm + T_KV + row * 128 + (colb ^ ((row & 7) * 16))) = *(uint32_t*)&hv;
        }
    }
    CP_WAIT0();                    // Q now resident
    __syncthreads();

    // ---- phase 2: ctx[s,e] = (1/8) sum_d qn[s,d] * KV[d,e] ----
    int rA_l = (lane & 7) + 8 * ((lane >> 3) & 1);
    int cA_l = 8 * (lane >> 4);
    int dB_l = (lane & 7) + 8 * ((lane >> 3) & 1);
    int eB2_l = 8 * (lane >> 4);

#pragma unroll
    for (int rep = 0; rep < 2; rep++) {
        int mt = warp + 8 * rep;
        if (mt > 12) break;
        int s0 = mt * 16;
        float acc2[8][4];
#pragma unroll
        for (int j = 0; j < 8; j++)
#pragma unroll
            for (int k = 0; k < 4; k++) acc2[j][k] = 0.0f;

#pragma unroll
        for (int kk = 0; kk < 4; kk++) {
            int kd0 = kk * 16;
            uint32_t a0, a1, a2, a3;
            {
                int r = s0 + rA_l;
                int dc = kd0 + cA_l;
                uint32_t addr = sb + T_Q + r * 128 + ((dc * 2) ^ ((r & 7) * 16));
                LDSM4(a0, a1, a2, a3, addr);
            }
            uint32_t bfr[8][2];
#pragma unroll
            for (int g = 0; g < 4; g++) {
                int dB = kd0 + dB_l;
                int eB = 16 * g + eB2_l;
                uint32_t addr = sb + T_KV + dB * 128 + ((eB * 2) ^ ((dB & 7) * 16));
                LDSM4T(bfr[2*g][0], bfr[2*g][1], bfr[2*g+1][0], bfr[2*g+1][1], addr);
            }
#pragma unroll
            for (int j = 0; j < 8; j++)
                MMA16816(acc2[j][0], acc2[j][1], acc2[j][2], acc2[j][3],
                         a0, a1, a2, a3, bfr[j][0], bfr[j][1]);
        }
        // store ctx rows (guard s < 200)
#pragma unroll
        for (int hr = 0; hr < 2; hr++) {
            int s = s0 + 8 * hr + gid;
            if (s < 200) {
                __half* cp = g_ctxh + ((size_t)b * 200 + s) * 512 + h * 64 + 2 * tig;
#pragma unroll
                for (int j = 0; j < 8; j++) {
                    __half2 hv = __floats2half2_rn(acc2[j][2*hr] * 0.125f,
                                                   acc2[j][2*hr+1] * 0.125f);
                    *(uint32_t*)(cp + 8 * j) = *(uint32_t*)&hv;
                }
            }
        }
    }
}

// ---------------------------------------------------------------------------
// out = LayerNorm(g_oh + g_hh)   (both residual inputs fp16)
// ---------------------------------------------------------------------------
__global__ void final_ln(const float* __restrict__ g, const float* __restrict__ bv_,
                         float* __restrict__ out) {
    size_t row = blockIdx.x;
    int t = threadIdx.x;
    uint2 ou = ((const uint2*)g_oh)[row * 128 + t];
    uint2 hu = ((const uint2*)g_hh)[row * 128 + t];
    float2 o01 = __half22float2(*(__half2*)&ou.x);
    float2 o23 = __half22float2(*(__half2*)&ou.y);
    float2 h01 = __half22float2(*(__half2*)&hu.x);
    float2 h23 = __half22float2(*(__half2*)&hu.y);
    float4 ov;
    ov.x = o01.x + h01.x; ov.y = o01.y + h01.y;
    ov.z = o23.x + h23.x; ov.w = o23.y + h23.y;
    float s  = ov.x + ov.y + ov.z + ov.w;
    float ss = ov.x*ov.x + ov.y*ov.y + ov.z*ov.z + ov.w*ov.w;
    block_reduce2_128(s, ss);
    float mu  = s * (1.0f / 512.0f);
    float var = ss * (1.0f / 512.0f) - mu * mu;
    float rstd = rsqrtf(var + 1e-12f);
    float4 gv = ((const float4*)g)[t];
    float4 bb = ((const float4*)bv_)[t];
    float4 o;
    o.x = (ov.x - mu) * rstd * gv.x + bb.x;
    o.y = (ov.y - mu) * rstd * gv.y + bb.y;
    o.z = (ov.z - mu) * rstd * gv.z + bb.z;
    o.w = (ov.w - mu) * rstd * gv.w + bb.w;
    ((float4*)out)[row * 128 + t] = o;
}

// ---------------------------------------------------------------------------
// Launch
// ---------------------------------------------------------------------------
extern "C" void kernel_launch(void* const* d_in, const int* in_sizes, int n_in,
                              void* d_out, int out_size) {
    const float* input = (const float*)d_in[0];
    const float* pos   = (const float*)d_in[1];
    // d_in[2] = attention_mask (unused by LinMHA)
    const float* Wq = (const float*)d_in[3];
    const float* bq = (const float*)d_in[4];
    const float* Wk = (const float*)d_in[5];
    const float* bk = (const float*)d_in[6];
    const float* Wv = (const float*)d_in[7];
    const float* bv = (const float*)d_in[8];
    const float* Wd = (const float*)d_in[9];
    const float* bd = (const float*)d_in[10];
    const float* lng = (const float*)d_in[11];
    const float* lnb = (const float*)d_in[12];
    float* out = (float*)d_out;

    static bool attr_set = false;
    if (!attr_set) {
        cudaFuncSetAttribute(gemm_f16, cudaFuncAttributeMaxDynamicSharedMemorySize, GEMM_SMEM);
        cudaFuncSetAttribute(fused_attn, cudaFuncAttributeMaxDynamicSharedMemorySize, ATTN_SMEM);
        attr_set = true;
    }

    pack_wt<<<dim3(16, 16, 4), dim3(32, 8)>>>(Wq, Wk, Wv, Wd);
    pack_bias<<<2, 256>>>(bq, bk, bv);
    add_ln<<<MM, 128>>>(input, pos, lng, lnb);
    gemm_f16<<<dim3(12, 800), 256, GEMM_SMEM>>>(0, nullptr);   // QKV + featmap
    fused_attn<<<4096, 256, ATTN_SMEM>>>();                    // kv + ctx
    gemm_f16<<<dim3(4, 800), 256, GEMM_SMEM>>>(1, bd);         // output proj
    final_ln<<<MM, 128>>>(lng, lnb, out);
}